// round 1
// baseline (speedup 1.0000x reference)
#include <cuda_runtime.h>
#include <cstddef>

#define BDIM 64
#define CIN  256
#define CO1  256
#define HWP  1024
#define LF2  1024

// ---------------- scratch (device globals; no allocation) ----------------
__device__ float g_h[(size_t)BDIM * CO1 * HWP];   //  64 MB conv1 output
__device__ float g_k[(size_t)BDIM * LF2 * HWP];   // 256 MB conv2 output / softmax in-place
__device__ float g_wT[49 * CIN * CO1];            // conv1 weights [tap][ci][co]
__device__ float g_w2T[CIN * LF2];                // conv2 weights [c][oc] * a1[c]
__device__ float g_beta2[LF2];
__device__ float g_a1[CO1], g_d1[CO1];
__device__ float g_a2[LF2], g_d2[LF2];

// ---------------- weight transpose: w1[co][ci][7][7] -> wT[tap][ci][co] ----------------
__global__ void transpose_w1_kernel(const float* __restrict__ w1) {
    int i = blockIdx.x * 256 + threadIdx.x;           // i indexes wT layout
    if (i >= 49 * 256 * 256) return;
    int co  = i & 255;
    int ci  = (i >> 8) & 255;
    int tap = i >> 16;
    g_wT[i] = w1[(co * 256 + ci) * 49 + tap];
}

// ---------------- conv1: 7x7 dilation-2 pad-6, implicit GEMM ----------------
// grid (512, 2), block 256. Block tile: 128 co x 128 pixels (one batch, 4 rows x 32 cols).
__global__ __launch_bounds__(256) void conv1_kernel(const float* __restrict__ x,
                                                    const float* __restrict__ b1) {
    __shared__ float Ws[32][128];
    __shared__ float Xs[32][132];

    int bt  = blockIdx.x;
    int b   = bt >> 3;
    int i0  = (bt & 7) << 2;          // first output row of this tile
    int co0 = blockIdx.y << 7;
    int tid = threadIdx.x;
    int tx  = tid & 15, ty = tid >> 4;

    const float* xb = x + (size_t)b * CIN * HWP;

    float acc[8][8];
#pragma unroll
    for (int m = 0; m < 8; m++)
#pragma unroll
        for (int n = 0; n < 8; n++) acc[m][n] = 0.f;

    for (int tap = 0; tap < 49; tap++) {
        int dp = 2 * (tap / 7) - 6;
        int dq = 2 * (tap % 7) - 6;
        const float* wsrc = g_wT + (size_t)tap * CIN * CO1 + co0;

        for (int kk = 0; kk < 8; kk++) {
            __syncthreads();
            // Ws[kc][m] = wT[(tap*256 + kk*32+kc)*256 + co0 + m]  (coalesced, float4)
            const float4* w4 = (const float4*)(wsrc + kk * 32 * CO1);
#pragma unroll
            for (int l = 0; l < 4; l++) {
                int idx = l * 256 + tid;
                int kc  = idx >> 5;
                int m4  = idx & 31;
                *(float4*)&Ws[kc][m4 * 4] = w4[kc * 64 + m4];
            }
            // Xs[kc][t] = x[b, kk*32+kc, i0 + t/32 + dp, (t%32) + dq] (zero OOB)
#pragma unroll
            for (int l = 0; l < 16; l++) {
                int idx = l * 256 + tid;
                int kc  = idx >> 7;
                int t   = idx & 127;
                int r   = t >> 5, j = t & 31;
                int u   = i0 + r + dp;
                int v   = j + dq;
                float val = 0.f;
                if ((unsigned)u < 32u && (unsigned)v < 32u)
                    val = xb[(kk * 32 + kc) * HWP + u * 32 + v];
                Xs[kc][t] = val;
            }
            __syncthreads();
#pragma unroll
            for (int k = 0; k < 32; k++) {
                float a[8], bb[8];
#pragma unroll
                for (int m = 0; m < 8; m++) a[m] = Ws[k][ty * 8 + m];
#pragma unroll
                for (int n = 0; n < 8; n++) bb[n] = Xs[k][tx * 8 + n];
#pragma unroll
                for (int m = 0; m < 8; m++)
#pragma unroll
                    for (int n = 0; n < 8; n++)
                        acc[m][n] = fmaf(a[m], bb[n], acc[m][n]);
            }
        }
    }

    int nbase = i0 * 32 + tx * 8;
#pragma unroll
    for (int m = 0; m < 8; m++) {
        int co = co0 + ty * 8 + m;
        float bias = b1[co];
        float* dst = g_h + ((size_t)(b * CO1 + co) << 10) + nbase;
#pragma unroll
        for (int n = 0; n < 8; n++) dst[n] = acc[m][n] + bias;
    }
}

// ---------------- BN stats: per-channel mean/var over (B,H,W) -> a,d ----------------
// grid = nchan, block = 256
__global__ void bn_stats_kernel(const float* __restrict__ data, int nchan,
                                const float* __restrict__ gamma,
                                const float* __restrict__ beta,
                                float* __restrict__ a, float* __restrict__ d) {
    int c = blockIdx.x;
    int tid = threadIdx.x;
    float s = 0.f, ss = 0.f;
    for (int b = 0; b < BDIM; b++) {
        const float* p = data + ((size_t)(b * nchan + c) << 10);
#pragma unroll
        for (int o = 0; o < 4; o++) {
            float v = p[tid + o * 256];
            s += v; ss += v * v;
        }
    }
    __shared__ float sh[256], sh2[256];
    sh[tid] = s; sh2[tid] = ss;
    __syncthreads();
    for (int st = 128; st > 0; st >>= 1) {
        if (tid < st) { sh[tid] += sh[tid + st]; sh2[tid] += sh2[tid + st]; }
        __syncthreads();
    }
    if (tid == 0) {
        float mean = sh[0] * (1.f / 65536.f);
        float var  = sh2[0] * (1.f / 65536.f) - mean * mean;
        float ai   = gamma[c] * rsqrtf(var + 1e-5f);
        a[c] = ai;
        d[c] = beta[c] - mean * ai;
    }
}

// ---------------- fold BN1 into conv2: w2T[c][oc] = w2[oc][c]*a1[c]; beta2[oc] ----------------
__global__ void fold2_kernel(const float* __restrict__ w2, const float* __restrict__ b2) {
    int oc = blockIdx.x;
    int c  = threadIdx.x;
    float wv = w2[oc * CIN + c];
    g_w2T[c * LF2 + oc] = wv * g_a1[c];
    __shared__ float sh[256];
    sh[c] = wv * g_d1[c];
    __syncthreads();
    for (int st = 128; st > 0; st >>= 1) {
        if (c < st) sh[c] += sh[c + st];
        __syncthreads();
    }
    if (c == 0) g_beta2[oc] = b2[oc] + sh[0];
}

// ---------------- conv2: 1x1 -> 1024ch GEMM ----------------
// grid (512, 8), block 256. Tile 128 oc x 128 pixels, K=256.
__global__ __launch_bounds__(256) void conv2_kernel() {
    __shared__ float Ws[32][128];
    __shared__ float Xs[32][132];

    int bt  = blockIdx.x;
    int b   = bt >> 3;
    int n0  = (bt & 7) << 7;
    int oc0 = blockIdx.y << 7;
    int tid = threadIdx.x;
    int tx  = tid & 15, ty = tid >> 4;

    float acc[8][8];
#pragma unroll
    for (int m = 0; m < 8; m++)
#pragma unroll
        for (int n = 0; n < 8; n++) acc[m][n] = 0.f;

    for (int kk = 0; kk < 8; kk++) {
        __syncthreads();
        const float4* w4 = (const float4*)(g_w2T + kk * 32 * LF2 + oc0);
        const float4* h4 = (const float4*)(g_h + ((size_t)(b * CO1 + kk * 32) << 10) + n0);
#pragma unroll
        for (int l = 0; l < 4; l++) {
            int idx = l * 256 + tid;
            int kc  = idx >> 5;
            int m4  = idx & 31;
            *(float4*)&Ws[kc][m4 * 4] = w4[kc * 256 + m4];
            *(float4*)&Xs[kc][m4 * 4] = h4[kc * 256 + m4];
        }
        __syncthreads();
#pragma unroll
        for (int k = 0; k < 32; k++) {
            float a[8], bb[8];
#pragma unroll
            for (int m = 0; m < 8; m++) a[m] = Ws[k][ty * 8 + m];
#pragma unroll
            for (int n = 0; n < 8; n++) bb[n] = Xs[k][tx * 8 + n];
#pragma unroll
            for (int m = 0; m < 8; m++)
#pragma unroll
                for (int n = 0; n < 8; n++)
                    acc[m][n] = fmaf(a[m], bb[n], acc[m][n]);
        }
    }

#pragma unroll
    for (int m = 0; m < 8; m++) {
        int oc = oc0 + ty * 8 + m;
        float beta = g_beta2[oc];
        float* dst = g_k + ((size_t)(b * LF2 + oc) << 10) + n0 + tx * 8;
#pragma unroll
        for (int n = 0; n < 8; n++) dst[n] = acc[m][n] + beta;
    }
}

// ---------------- BN2 + softmax over 1024 channels (in place on g_k) ----------------
// Logits are BN-standardized (mu=0, sigma=1 per channel), so exp is overflow-safe
// without max subtraction (|logit| would need >80 to overflow; BN bounds ~a few sigma).
// grid 256, block 256; thread = one pixel, strided channel reads are coalesced across threads.
__global__ void softmax_kernel() {
    __shared__ float sa[LF2], sd[LF2];
    int tid = threadIdx.x;
    for (int i = tid; i < LF2; i += 256) { sa[i] = g_a2[i]; sd[i] = g_d2[i]; }
    __syncthreads();
    int pix = blockIdx.x * 256 + tid;
    int b = pix >> 10, n = pix & 1023;
    float* base = g_k + ((size_t)b << 20) + n;
    float s = 0.f;
    for (int oc = 0; oc < LF2; oc++) {
        float v = base[(size_t)oc << 10] * sa[oc] + sd[oc];
        s += __expf(v);
    }
    float inv = 1.f / s;
    for (int oc = 0; oc < LF2; oc++) {
        float v = base[(size_t)oc << 10] * sa[oc] + sd[oc];
        base[(size_t)oc << 10] = __expf(v) * inv;
    }
}

// ---------------- output einsum: y[b,n,c] = sum_uv softmax[b,uv,n] * x[b,c,uv] ----------------
// grid (512, 2), block 256. Tile 128 n x 128 c, K=1024 (uv).
__global__ __launch_bounds__(256) void out_kernel(const float* __restrict__ x,
                                                  float* __restrict__ out) {
    __shared__ float As[32][132];
    __shared__ float Bs[32][132];

    int bt = blockIdx.x;
    int b  = bt >> 3;
    int n0 = (bt & 7) << 7;
    int c0 = blockIdx.y << 7;
    int tid = threadIdx.x;
    int tx = tid & 15, ty = tid >> 4;

    const float* S  = g_k + ((size_t)b << 20);
    const float* xb = x + (size_t)b * CIN * HWP;

    float acc[8][8];
#pragma unroll
    for (int m = 0; m < 8; m++)
#pragma unroll
        for (int n = 0; n < 8; n++) acc[m][n] = 0.f;

    for (int kk = 0; kk < 32; kk++) {
        __syncthreads();
        // As[kc][nn] = S[(kk*32+kc)*1024 + n0 + nn]
        const float4* s4 = (const float4*)(S + (size_t)kk * 32 * HWP + n0);
#pragma unroll
        for (int l = 0; l < 4; l++) {
            int idx = l * 256 + tid;
            int kc  = idx >> 5;
            int t4  = idx & 31;
            *(float4*)&As[kc][t4 * 4] = s4[kc * 256 + t4];
        }
        // Bs[kc][cc] = x[b, c0+cc, kk*32+kc]  (loaded along uv, stored transposed)
#pragma unroll
        for (int l = 0; l < 4; l++) {
            int idx = l * 256 + tid;
            int cc  = idx >> 3;
            int u4  = idx & 7;
            float4 v = *(const float4*)(xb + (size_t)(c0 + cc) * HWP + kk * 32 + u4 * 4);
            Bs[u4 * 4 + 0][cc] = v.x;
            Bs[u4 * 4 + 1][cc] = v.y;
            Bs[u4 * 4 + 2][cc] = v.z;
            Bs[u4 * 4 + 3][cc] = v.w;
        }
        __syncthreads();
#pragma unroll
        for (int k = 0; k < 32; k++) {
            float a[8], bb[8];
#pragma unroll
            for (int m = 0; m < 8; m++) a[m] = As[k][ty * 8 + m];
#pragma unroll
            for (int n = 0; n < 8; n++) bb[n] = Bs[k][tx * 8 + n];
#pragma unroll
            for (int m = 0; m < 8; m++)
#pragma unroll
                for (int n = 0; n < 8; n++)
                    acc[m][n] = fmaf(a[m], bb[n], acc[m][n]);
        }
    }

#pragma unroll
    for (int m = 0; m < 8; m++) {
        float* dst = out + ((size_t)b << 18) + (size_t)(n0 + ty * 8 + m) * 256 + c0 + tx * 8;
#pragma unroll
        for (int n = 0; n < 8; n++) dst[n] = acc[m][n];
    }
}

// ---------------- launch ----------------
extern "C" void kernel_launch(void* const* d_in, const int* in_sizes, int n_in,
                              void* d_out, int out_size) {
    const float* x   = (const float*)d_in[0];
    const float* w1  = (const float*)d_in[1];
    const float* b1  = (const float*)d_in[2];
    const float* g1  = (const float*)d_in[3];
    const float* bb1 = (const float*)d_in[4];
    const float* w2  = (const float*)d_in[5];
    const float* b2  = (const float*)d_in[6];
    const float* g2  = (const float*)d_in[7];
    const float* bb2 = (const float*)d_in[8];
    float* out = (float*)d_out;

    void *p_h, *p_k, *p_a1, *p_d1, *p_a2, *p_d2;
    cudaGetSymbolAddress(&p_h,  g_h);
    cudaGetSymbolAddress(&p_k,  g_k);
    cudaGetSymbolAddress(&p_a1, g_a1);
    cudaGetSymbolAddress(&p_d1, g_d1);
    cudaGetSymbolAddress(&p_a2, g_a2);
    cudaGetSymbolAddress(&p_d2, g_d2);

    transpose_w1_kernel<<<12544, 256>>>(w1);
    conv1_kernel<<<dim3(512, 2), 256>>>(x, b1);
    bn_stats_kernel<<<256, 256>>>((const float*)p_h, CO1, g1, bb1,
                                  (float*)p_a1, (float*)p_d1);
    fold2_kernel<<<1024, 256>>>(w2, b2);
    conv2_kernel<<<dim3(512, 8), 256>>>();
    bn_stats_kernel<<<1024, 256>>>((const float*)p_k, LF2, g2, bb2,
                                   (float*)p_a2, (float*)p_d2);
    softmax_kernel<<<256, 256>>>();
    out_kernel<<<dim3(512, 2), 256>>>(x, out);
}

// round 3
// speedup vs baseline: 2.1006x; 2.1006x over previous
#include <cuda_runtime.h>
#include <cuda_bf16.h>
#include <cstdint>
#include <cstddef>

#define BDIM 64
#define CIN  256
#define CO1  256
#define HWP  1024
#define LF2  1024

// ---------------- scratch (device globals; no allocation) ----------------
__device__ float g_h[(size_t)BDIM * CO1 * HWP];   //  64 MB conv1 output (pre-BN, +bias)
__device__ float g_k[(size_t)BDIM * LF2 * HWP];   // 256 MB conv2 output / softmax in-place
__device__ float g_w2T[CIN * LF2];                // conv2 weights [c][oc] * a1[c]
__device__ float g_beta2[LF2];
__device__ float g_a1[CO1], g_d1[CO1];
__device__ float g_a2[LF2], g_d2[LF2];
// bf16 split operands for conv1 tensor-core path
__device__ __align__(16) __nv_bfloat16 g_whi [49 * CO1 * CIN];            // [tap][co][ci]
__device__ __align__(16) __nv_bfloat16 g_wmid[49 * CO1 * CIN];
__device__ __align__(16) __nv_bfloat16 g_xhi [(size_t)BDIM * HWP * CIN];  // [b][uv][ci]
__device__ __align__(16) __nv_bfloat16 g_xmid[(size_t)BDIM * HWP * CIN];

// ---------------- family-common PTX helpers (mma.sync / ldmatrix / cp.async) ----------------
__device__ __forceinline__ uint32_t smem_u32(const void* p) {
    uint32_t a;
    asm("{ .reg .u64 t; cvta.to.shared.u64 t, %1; cvt.u32.u64 %0, t; }" : "=r"(a) : "l"(p));
    return a;
}
__device__ __forceinline__ void cp_async16(uint32_t dst, const void* src, uint32_t srcsize) {
    asm volatile("cp.async.cg.shared.global [%0], [%1], 16, %2;"
                 :: "r"(dst), "l"(src), "r"(srcsize));
}
__device__ __forceinline__ void cp_commit() {
    asm volatile("cp.async.commit_group;");
}
template <int N> __device__ __forceinline__ void cp_wait() {
    asm volatile("cp.async.wait_group %0;" :: "n"(N));
}
__device__ __forceinline__ void ldsm4(uint32_t* r, uint32_t addr) {
    asm volatile("ldmatrix.sync.aligned.m8n8.x4.shared.b16 {%0,%1,%2,%3}, [%4];"
                 : "=r"(r[0]), "=r"(r[1]), "=r"(r[2]), "=r"(r[3]) : "r"(addr));
}
__device__ __forceinline__ void mma_bf16(float* c, const uint32_t* a, const uint32_t* b) {
    asm volatile(
        "mma.sync.aligned.m16n8k16.row.col.f32.bf16.bf16.f32 "
        "{%0,%1,%2,%3}, {%4,%5,%6,%7}, {%8,%9}, {%0,%1,%2,%3};"
        : "+f"(c[0]), "+f"(c[1]), "+f"(c[2]), "+f"(c[3])
        : "r"(a[0]), "r"(a[1]), "r"(a[2]), "r"(a[3]), "r"(b[0]), "r"(b[1]));
}

// ---------------- prep: split w1 -> bf16 hi/mid, layout [tap][co][ci] ----------------
__global__ void split_w1_kernel(const float* __restrict__ w1) {
    int i = blockIdx.x * 256 + threadIdx.x;
    if (i >= 49 * 256 * 256) return;
    int ci = i & 255, co = (i >> 8) & 255, tap = i >> 16;
    float v = w1[(co * 256 + ci) * 49 + tap];
    __nv_bfloat16 hi = __float2bfloat16(v);
    g_whi[i]  = hi;
    g_wmid[i] = __float2bfloat16(v - __bfloat162float(hi));
}

// ---------------- prep: transpose+split x[b][ci][uv] -> xT[b][uv][ci] bf16 hi/mid ----------------
__global__ void split_x_kernel(const float* __restrict__ x) {
    __shared__ float t[32][33];
    int b   = blockIdx.z;
    int uv0 = blockIdx.x << 5;
    int ci0 = blockIdx.y << 5;
    int tx = threadIdx.x, ty = threadIdx.y;   // (32, 8)
#pragma unroll
    for (int r = 0; r < 4; r++) {
        int ci = ci0 + ty + r * 8;
        t[ty + r * 8][tx] = x[((size_t)(b * 256 + ci) << 10) + uv0 + tx];
    }
    __syncthreads();
#pragma unroll
    for (int r = 0; r < 4; r++) {
        int uv = uv0 + ty + r * 8;
        float v = t[tx][ty + r * 8];
        __nv_bfloat16 hi = __float2bfloat16(v);
        size_t o = ((size_t)b << 18) + ((size_t)uv << 8) + ci0 + tx;
        g_xhi[o]  = hi;
        g_xmid[o] = __float2bfloat16(v - __bfloat162float(hi));
    }
}

// ---------------- conv1 via mma.sync bf16 3-product split ----------------
// grid (512, 2), block 256 (8 warps). CTA tile: 128 co x 128 pixels (batch b, rows i0..i0+3).
// K loop: 49 taps x 4 ci-chunks of 64 = 196 stages, cp.async double-buffered.
// Stage layout (4 tiles, each 128 rows x 64 bf16, row stride 144B): Ahi | Amid | Bhi | Bmid.
#define C1_TILE   18432            // 128 * 144
#define C1_STAGE  (4 * C1_TILE)    // 73728
#define C1_SMEM   (2 * C1_STAGE)   // 147456

__device__ __forceinline__ void conv1_issue_stage(
    uint32_t base, int b, int i0, int co0, int tap, int kc, int tid)
{
    const int dp = (tap / 7) * 2 - 6;
    const int dq = (tap % 7) * 2 - 6;
    const __nv_bfloat16* srcAh = g_whi  + ((size_t)tap << 16) + ((size_t)co0 << 8) + (kc << 6);
    const __nv_bfloat16* srcAm = g_wmid + ((size_t)tap << 16) + ((size_t)co0 << 8) + (kc << 6);
    const __nv_bfloat16* xh = g_xhi  + ((size_t)b << 18) + (kc << 6);
    const __nv_bfloat16* xm = g_xmid + ((size_t)b << 18) + (kc << 6);
#pragma unroll
    for (int l = 0; l < 4; l++) {
        int idx = l * 256 + tid;
        int row = idx >> 3, c16 = idx & 7;       // row 0..127, 16B chunk 0..7
        uint32_t off = (uint32_t)(row * 144 + c16 * 16);
        // A tiles (always in-bounds)
        cp_async16(base + off,            srcAh + row * 256 + c16 * 8, 16);
        cp_async16(base + C1_TILE + off,  srcAm + row * 256 + c16 * 8, 16);
        // B tiles (zero-fill out-of-image taps)
        int u = i0 + (row >> 5) + dp;
        int v = (row & 31) + dq;
        bool in = ((unsigned)u < 32u) && ((unsigned)v < 32u);
        int pix = in ? (u * 32 + v) : 0;
        uint32_t sz = in ? 16u : 0u;
        cp_async16(base + 2 * C1_TILE + off, xh + ((size_t)pix << 8) + c16 * 8, sz);
        cp_async16(base + 3 * C1_TILE + off, xm + ((size_t)pix << 8) + c16 * 8, sz);
    }
}

__global__ __launch_bounds__(256, 1) void conv1_mma_kernel(const float* __restrict__ b1) {
    extern __shared__ char smem[];
    const uint32_t sb = smem_u32(smem);
    const int tid  = threadIdx.x;
    const int lane = tid & 31;
    const int wid  = tid >> 5;
    const int wm   = wid >> 1;          // 0..3: warp row (32 co each)
    const int wn   = wid & 1;           // 0..1: warp col (64 px each)
    const int bt   = blockIdx.x;
    const int b    = bt >> 3;
    const int i0   = (bt & 7) << 2;
    const int co0  = blockIdx.y << 7;

    float acc[2][8][4];
#pragma unroll
    for (int mf = 0; mf < 2; mf++)
#pragma unroll
        for (int nf = 0; nf < 8; nf++)
#pragma unroll
            for (int e = 0; e < 4; e++) acc[mf][nf][e] = 0.f;

    // fragment base addresses (per-warp, per-lane; col part added per k-step)
    const uint32_t a_rowoff = (uint32_t)((wm * 32 + (lane & 15)) * 144 + (lane >> 4) * 16);
    const uint32_t b_rowoff = (uint32_t)((wn * 64 + (lane & 15)) * 144 + (lane >> 4) * 16);

    // prologue: stage 0
    conv1_issue_stage(sb, b, i0, co0, 0, 0, tid);
    cp_commit();

    int it = 0;
    for (int tap = 0; tap < 49; tap++) {
        for (int kc = 0; kc < 4; kc++, it++) {
            // issue next stage into the other buffer
            if (it < 195) {
                int nit = it + 1;
                conv1_issue_stage(sb + ((nit & 1) ? C1_STAGE : 0),
                                  b, i0, co0, nit >> 2, nit & 3, tid);
                cp_commit();
                cp_wait<1>();
            } else {
                cp_wait<0>();
            }
            __syncthreads();

            const uint32_t cur = sb + ((it & 1) ? C1_STAGE : 0);
#pragma unroll
            for (int ks = 0; ks < 4; ks++) {
                const uint32_t koff = (uint32_t)(ks * 32);
                uint32_t ah[2][4], am[2][4], bh[8][2], bm[8][2];
#pragma unroll
                for (int mf = 0; mf < 2; mf++) {
                    uint32_t addr = cur + a_rowoff + (uint32_t)(mf * 16 * 144) + koff;
                    ldsm4(ah[mf], addr);
                    ldsm4(am[mf], addr + C1_TILE);
                }
#pragma unroll
                for (int nf2 = 0; nf2 < 4; nf2++) {
                    uint32_t r[4];
                    uint32_t addr = cur + 2 * C1_TILE + b_rowoff + (uint32_t)(nf2 * 16 * 144) + koff;
                    ldsm4(r, addr);
                    bh[nf2 * 2][0] = r[0]; bh[nf2 * 2][1] = r[2];
                    bh[nf2 * 2 + 1][0] = r[1]; bh[nf2 * 2 + 1][1] = r[3];
                    ldsm4(r, addr + C1_TILE);
                    bm[nf2 * 2][0] = r[0]; bm[nf2 * 2][1] = r[2];
                    bm[nf2 * 2 + 1][0] = r[1]; bm[nf2 * 2 + 1][1] = r[3];
                }
#pragma unroll
                for (int mf = 0; mf < 2; mf++)
#pragma unroll
                    for (int nf = 0; nf < 8; nf++) {
                        mma_bf16(acc[mf][nf], ah[mf], bh[nf]);
                        mma_bf16(acc[mf][nf], ah[mf], bm[nf]);
                        mma_bf16(acc[mf][nf], am[mf], bh[nf]);
                    }
            }
            __syncthreads();
        }
    }

    // epilogue: acc -> g_h (+bias). Thread owns co rows {R, R+8}, px cols {C, C+1} per frag.
#pragma unroll
    for (int mf = 0; mf < 2; mf++) {
        int co = co0 + wm * 32 + mf * 16 + (lane >> 2);
        float bias0 = b1[co];
        float bias8 = b1[co + 8];
        float* row0 = g_h + ((size_t)(b * CO1 + co) << 10) + i0 * 32;
        float* row8 = row0 + ((size_t)8 << 10);
#pragma unroll
        for (int nf = 0; nf < 8; nf++) {
            int C = wn * 64 + nf * 8 + (lane & 3) * 2;
            float2 v0 = make_float2(acc[mf][nf][0] + bias0, acc[mf][nf][1] + bias0);
            float2 v8 = make_float2(acc[mf][nf][2] + bias8, acc[mf][nf][3] + bias8);
            *(float2*)(row0 + C) = v0;
            *(float2*)(row8 + C) = v8;
        }
    }
}

// ---------------- BN stats: per-channel mean/var over (B,H,W) -> a,d ----------------
__global__ void bn_stats_kernel(const float* __restrict__ data, int nchan,
                                const float* __restrict__ gamma,
                                const float* __restrict__ beta,
                                float* __restrict__ a, float* __restrict__ d) {
    int c = blockIdx.x;
    int tid = threadIdx.x;
    float s = 0.f, ss = 0.f;
    for (int b = 0; b < BDIM; b++) {
        const float* p = data + ((size_t)(b * nchan + c) << 10);
#pragma unroll
        for (int o = 0; o < 4; o++) {
            float v = p[tid + o * 256];
            s += v; ss += v * v;
        }
    }
    __shared__ float sh[256], sh2[256];
    sh[tid] = s; sh2[tid] = ss;
    __syncthreads();
    for (int st = 128; st > 0; st >>= 1) {
        if (tid < st) { sh[tid] += sh[tid + st]; sh2[tid] += sh2[tid + st]; }
        __syncthreads();
    }
    if (tid == 0) {
        float mean = sh[0] * (1.f / 65536.f);
        float var  = sh2[0] * (1.f / 65536.f) - mean * mean;
        float ai   = gamma[c] * rsqrtf(var + 1e-5f);
        a[c] = ai;
        d[c] = beta[c] - mean * ai;
    }
}

// ---------------- fold BN1 into conv2 ----------------
__global__ void fold2_kernel(const float* __restrict__ w2, const float* __restrict__ b2) {
    int oc = blockIdx.x;
    int c  = threadIdx.x;
    float wv = w2[oc * CIN + c];
    g_w2T[c * LF2 + oc] = wv * g_a1[c];
    __shared__ float sh[256];
    sh[c] = wv * g_d1[c];
    __syncthreads();
    for (int st = 128; st > 0; st >>= 1) {
        if (c < st) sh[c] += sh[c + st];
        __syncthreads();
    }
    if (c == 0) g_beta2[oc] = b2[oc] + sh[0];
}

// ---------------- conv2: 1x1 -> 1024ch GEMM (fp32) ----------------
__global__ __launch_bounds__(256) void conv2_kernel() {
    __shared__ float Ws[32][128];
    __shared__ float Xs[32][132];

    int bt  = blockIdx.x;
    int b   = bt >> 3;
    int n0  = (bt & 7) << 7;
    int oc0 = blockIdx.y << 7;
    int tid = threadIdx.x;
    int tx  = tid & 15, ty = tid >> 4;

    float acc[8][8];
#pragma unroll
    for (int m = 0; m < 8; m++)
#pragma unroll
        for (int n = 0; n < 8; n++) acc[m][n] = 0.f;

    for (int kk = 0; kk < 8; kk++) {
        __syncthreads();
        const float4* w4 = (const float4*)(g_w2T + kk * 32 * LF2 + oc0);
        const float4* h4 = (const float4*)(g_h + ((size_t)(b * CO1 + kk * 32) << 10) + n0);
#pragma unroll
        for (int l = 0; l < 4; l++) {
            int idx = l * 256 + tid;
            int kc  = idx >> 5;
            int m4  = idx & 31;
            *(float4*)&Ws[kc][m4 * 4] = w4[kc * 256 + m4];
            *(float4*)&Xs[kc][m4 * 4] = h4[kc * 256 + m4];
        }
        __syncthreads();
#pragma unroll
        for (int k = 0; k < 32; k++) {
            float a[8], bb[8];
#pragma unroll
            for (int m = 0; m < 8; m++) a[m] = Ws[k][ty * 8 + m];
#pragma unroll
            for (int n = 0; n < 8; n++) bb[n] = Xs[k][tx * 8 + n];
#pragma unroll
            for (int m = 0; m < 8; m++)
#pragma unroll
                for (int n = 0; n < 8; n++)
                    acc[m][n] = fmaf(a[m], bb[n], acc[m][n]);
        }
    }

#pragma unroll
    for (int m = 0; m < 8; m++) {
        int oc = oc0 + ty * 8 + m;
        float beta = g_beta2[oc];
        float* dst = g_k + ((size_t)(b * LF2 + oc) << 10) + n0 + tx * 8;
#pragma unroll
        for (int n = 0; n < 8; n++) dst[n] = acc[m][n] + beta;
    }
}

// ---------------- BN2 + softmax over 1024 channels (in place) ----------------
__global__ void softmax_kernel() {
    __shared__ float sa[LF2], sd[LF2];
    int tid = threadIdx.x;
    for (int i = tid; i < LF2; i += 256) { sa[i] = g_a2[i]; sd[i] = g_d2[i]; }
    __syncthreads();
    int pix = blockIdx.x * 256 + tid;
    int b = pix >> 10, n = pix & 1023;
    float* base = g_k + ((size_t)b << 20) + n;
    float s = 0.f;
    for (int oc = 0; oc < LF2; oc++) {
        float v = base[(size_t)oc << 10] * sa[oc] + sd[oc];
        s += __expf(v);
    }
    float inv = 1.f / s;
    for (int oc = 0; oc < LF2; oc++) {
        float v = base[(size_t)oc << 10] * sa[oc] + sd[oc];
        base[(size_t)oc << 10] = __expf(v) * inv;
    }
}

// ---------------- output einsum (fp32 SGEMM) ----------------
__global__ __launch_bounds__(256) void out_kernel(const float* __restrict__ x,
                                                  float* __restrict__ out) {
    __shared__ float As[32][132];
    __shared__ float Bs[32][132];

    int bt = blockIdx.x;
    int b  = bt >> 3;
    int n0 = (bt & 7) << 7;
    int c0 = blockIdx.y << 7;
    int tid = threadIdx.x;
    int tx = tid & 15, ty = tid >> 4;

    const float* S  = g_k + ((size_t)b << 20);
    const float* xb = x + (size_t)b * CIN * HWP;

    float acc[8][8];
#pragma unroll
    for (int m = 0; m < 8; m++)
#pragma unroll
        for (int n = 0; n < 8; n++) acc[m][n] = 0.f;

    for (int kk = 0; kk < 32; kk++) {
        __syncthreads();
        const float4* s4 = (const float4*)(S + (size_t)kk * 32 * HWP + n0);
#pragma unroll
        for (int l = 0; l < 4; l++) {
            int idx = l * 256 + tid;
            int kc  = idx >> 5;
            int t4  = idx & 31;
            *(float4*)&As[kc][t4 * 4] = s4[kc * 256 + t4];
        }
#pragma unroll
        for (int l = 0; l < 4; l++) {
            int idx = l * 256 + tid;
            int cc  = idx >> 3;
            int u4  = idx & 7;
            float4 v = *(const float4*)(xb + (size_t)(c0 + cc) * HWP + kk * 32 + u4 * 4);
            Bs[u4 * 4 + 0][cc] = v.x;
            Bs[u4 * 4 + 1][cc] = v.y;
            Bs[u4 * 4 + 2][cc] = v.z;
            Bs[u4 * 4 + 3][cc] = v.w;
        }
        __syncthreads();
#pragma unroll
        for (int k = 0; k < 32; k++) {
            float a[8], bb[8];
#pragma unroll
            for (int m = 0; m < 8; m++) a[m] = As[k][ty * 8 + m];
#pragma unroll
            for (int n = 0; n < 8; n++) bb[n] = Bs[k][tx * 8 + n];
#pragma unroll
            for (int m = 0; m < 8; m++)
#pragma unroll
                for (int n = 0; n < 8; n++)
                    acc[m][n] = fmaf(a[m], bb[n], acc[m][n]);
        }
    }

#pragma unroll
    for (int m = 0; m < 8; m++) {
        float* dst = out + ((size_t)b << 18) + (size_t)(n0 + ty * 8 + m) * 256 + c0 + tx * 8;
#pragma unroll
        for (int n = 0; n < 8; n++) dst[n] = acc[m][n];
    }
}

// ---------------- launch ----------------
extern "C" void kernel_launch(void* const* d_in, const int* in_sizes, int n_in,
                              void* d_out, int out_size) {
    const float* x   = (const float*)d_in[0];
    const float* w1  = (const float*)d_in[1];
    const float* b1  = (const float*)d_in[2];
    const float* g1  = (const float*)d_in[3];
    const float* bb1 = (const float*)d_in[4];
    const float* w2  = (const float*)d_in[5];
    const float* b2  = (const float*)d_in[6];
    const float* g2  = (const float*)d_in[7];
    const float* bb2 = (const float*)d_in[8];
    float* out = (float*)d_out;

    void *p_h, *p_k, *p_a1, *p_d1, *p_a2, *p_d2;
    cudaGetSymbolAddress(&p_h,  g_h);
    cudaGetSymbolAddress(&p_k,  g_k);
    cudaGetSymbolAddress(&p_a1, g_a1);
    cudaGetSymbolAddress(&p_d1, g_d1);
    cudaGetSymbolAddress(&p_a2, g_a2);
    cudaGetSymbolAddress(&p_d2, g_d2);

    cudaFuncSetAttribute(conv1_mma_kernel,
                         cudaFuncAttributeMaxDynamicSharedMemorySize, C1_SMEM);

    split_w1_kernel<<<12544, 256>>>(w1);
    split_x_kernel<<<dim3(32, 8, 64), dim3(32, 8)>>>(x);
    conv1_mma_kernel<<<dim3(512, 2), 256, C1_SMEM>>>(b1);
    bn_stats_kernel<<<256, 256>>>((const float*)p_h, CO1, g1, bb1,
                                  (float*)p_a1, (float*)p_d1);
    fold2_kernel<<<1024, 256>>>(w2, b2);
    conv2_kernel<<<dim3(512, 8), 256>>>();
    bn_stats_kernel<<<1024, 256>>>((const float*)p_k, LF2, g2, bb2,
                                   (float*)p_a2, (float*)p_d2);
    softmax_kernel<<<256, 256>>>();
    out_kernel<<<dim3(512, 2), 256>>>(x, out);
}

// round 4
// speedup vs baseline: 2.4723x; 1.1770x over previous
#include <cuda_runtime.h>
#include <cuda_bf16.h>
#include <cstdint>
#include <cstddef>

#define BDIM 64
#define CIN  256
#define CO1  256
#define HWP  1024
#define LF2  1024

// ---------------- scratch (device globals; no allocation) ----------------
__device__ float g_kT[(size_t)BDIM * HWP * LF2];     // conv2 output, [b][n][oc] fp32 (268MB)
__device__ float g_w2beta[LF2];
__device__ float g_a1[CO1], g_d1[CO1];
__device__ float g_a2[LF2], g_d2[LF2];
__device__ float g_p1s[256 * 256],  g_p1ss[256 * 256];
__device__ float g_p2s[256 * 1024], g_p2ss[256 * 1024];
// conv1 operands
__device__ __align__(16) __nv_bfloat16 g_whi [49 * CO1 * CIN];            // [tap][co][ci]
__device__ __align__(16) __nv_bfloat16 g_wmid[49 * CO1 * CIN];
__device__ __align__(16) __nv_bfloat16 g_xhi [(size_t)BDIM * HWP * CIN];  // [b][uv][ci]
__device__ __align__(16) __nv_bfloat16 g_xmid[(size_t)BDIM * HWP * CIN];
// out-GEMM B operand: x split, original layout [b][ci][uv]
__device__ __align__(16) __nv_bfloat16 g_xchi [(size_t)BDIM * CIN * HWP];
__device__ __align__(16) __nv_bfloat16 g_xcmid[(size_t)BDIM * CIN * HWP];
// conv1 output transposed split: [b][px][c]
__device__ __align__(16) __nv_bfloat16 g_hThi [(size_t)BDIM * HWP * CIN];
__device__ __align__(16) __nv_bfloat16 g_hTmid[(size_t)BDIM * HWP * CIN];
// conv2 folded weights split: [oc][c]
__device__ __align__(16) __nv_bfloat16 g_w2fhi [LF2 * CIN];
__device__ __align__(16) __nv_bfloat16 g_w2fmid[LF2 * CIN];
// softmax output transposed split: [b][n][uv]
__device__ __align__(16) __nv_bfloat16 g_sThi [(size_t)BDIM * HWP * LF2];
__device__ __align__(16) __nv_bfloat16 g_sTmid[(size_t)BDIM * HWP * LF2];

// ---------------- family-common PTX helpers ----------------
__device__ __forceinline__ uint32_t smem_u32(const void* p) {
    uint32_t a;
    asm("{ .reg .u64 t; cvta.to.shared.u64 t, %1; cvt.u32.u64 %0, t; }" : "=r"(a) : "l"(p));
    return a;
}
__device__ __forceinline__ void cp_async16(uint32_t dst, const void* src, uint32_t srcsize) {
    asm volatile("cp.async.cg.shared.global [%0], [%1], 16, %2;"
                 :: "r"(dst), "l"(src), "r"(srcsize));
}
__device__ __forceinline__ void cp_commit() {
    asm volatile("cp.async.commit_group;");
}
template <int N> __device__ __forceinline__ void cp_wait() {
    asm volatile("cp.async.wait_group %0;" :: "n"(N));
}
__device__ __forceinline__ void ldsm4(uint32_t* r, uint32_t addr) {
    asm volatile("ldmatrix.sync.aligned.m8n8.x4.shared.b16 {%0,%1,%2,%3}, [%4];"
                 : "=r"(r[0]), "=r"(r[1]), "=r"(r[2]), "=r"(r[3]) : "r"(addr));
}
__device__ __forceinline__ void mma_bf16(float* c, const uint32_t* a, const uint32_t* b) {
    asm volatile(
        "mma.sync.aligned.m16n8k16.row.col.f32.bf16.bf16.f32 "
        "{%0,%1,%2,%3}, {%4,%5,%6,%7}, {%8,%9}, {%0,%1,%2,%3};"
        : "+f"(c[0]), "+f"(c[1]), "+f"(c[2]), "+f"(c[3])
        : "r"(a[0]), "r"(a[1]), "r"(a[2]), "r"(a[3]), "r"(b[0]), "r"(b[1]));
}

// ---------------- prep: split w1 -> bf16 hi/mid, layout [tap][co][ci] ----------------
__global__ void split_w1_kernel(const float* __restrict__ w1) {
    int i = blockIdx.x * 256 + threadIdx.x;
    if (i >= 49 * 256 * 256) return;
    int ci = i & 255, co = (i >> 8) & 255, tap = i >> 16;
    float v = w1[(co * 256 + ci) * 49 + tap];
    __nv_bfloat16 hi = __float2bfloat16(v);
    g_whi[i]  = hi;
    g_wmid[i] = __float2bfloat16(v - __bfloat162float(hi));
}

// ---------------- prep: split x -> transposed [b][uv][ci] AND original [b][ci][uv] ----------------
__global__ void split_x_kernel(const float* __restrict__ x) {
    __shared__ float t[32][33];
    int b   = blockIdx.z;
    int uv0 = blockIdx.x << 5;
    int ci0 = blockIdx.y << 5;
    int tx = threadIdx.x, ty = threadIdx.y;   // (32, 8)
#pragma unroll
    for (int r = 0; r < 4; r++) {
        int ci = ci0 + ty + r * 8;
        float v = x[((size_t)(b * 256 + ci) << 10) + uv0 + tx];
        t[ty + r * 8][tx] = v;
        __nv_bfloat16 hi = __float2bfloat16(v);
        size_t o = ((size_t)(b * 256 + ci) << 10) + uv0 + tx;
        g_xchi[o]  = hi;
        g_xcmid[o] = __float2bfloat16(v - __bfloat162float(hi));
    }
    __syncthreads();
#pragma unroll
    for (int r = 0; r < 4; r++) {
        int uv = uv0 + ty + r * 8;
        float v = t[tx][ty + r * 8];
        __nv_bfloat16 hi = __float2bfloat16(v);
        size_t o = ((size_t)b << 18) + ((size_t)uv << 8) + ci0 + tx;
        g_xhi[o]  = hi;
        g_xmid[o] = __float2bfloat16(v - __bfloat162float(hi));
    }
}

// ---------------- conv1 via mma.sync bf16 3-product split ----------------
#define C1_TILE   18432            // 128 * 144
#define C1_STAGE  (4 * C1_TILE)    // 73728
#define C1_SMEM   (2 * C1_STAGE)   // 147456

__device__ __forceinline__ void conv1_issue_stage(
    uint32_t base, int b, int i0, int co0, int tap, int kc, int tid)
{
    const int dp = (tap / 7) * 2 - 6;
    const int dq = (tap % 7) * 2 - 6;
    const __nv_bfloat16* srcAh = g_whi  + ((size_t)tap << 16) + ((size_t)co0 << 8) + (kc << 6);
    const __nv_bfloat16* srcAm = g_wmid + ((size_t)tap << 16) + ((size_t)co0 << 8) + (kc << 6);
    const __nv_bfloat16* xh = g_xhi  + ((size_t)b << 18) + (kc << 6);
    const __nv_bfloat16* xm = g_xmid + ((size_t)b << 18) + (kc << 6);
#pragma unroll
    for (int l = 0; l < 4; l++) {
        int idx = l * 256 + tid;
        int row = idx >> 3, c16 = idx & 7;
        uint32_t off = (uint32_t)(row * 144 + c16 * 16);
        cp_async16(base + off,            srcAh + row * 256 + c16 * 8, 16);
        cp_async16(base + C1_TILE + off,  srcAm + row * 256 + c16 * 8, 16);
        int u = i0 + (row >> 5) + dp;
        int v = (row & 31) + dq;
        bool in = ((unsigned)u < 32u) && ((unsigned)v < 32u);
        int pix = in ? (u * 32 + v) : 0;
        uint32_t sz = in ? 16u : 0u;
        cp_async16(base + 2 * C1_TILE + off, xh + ((size_t)pix << 8) + c16 * 8, sz);
        cp_async16(base + 3 * C1_TILE + off, xm + ((size_t)pix << 8) + c16 * 8, sz);
    }
}

__global__ __launch_bounds__(256, 1) void conv1_mma_kernel(const float* __restrict__ b1) {
    extern __shared__ char smem[];
    const uint32_t sb = smem_u32(smem);
    const int tid  = threadIdx.x;
    const int lane = tid & 31;
    const int wid  = tid >> 5;
    const int wm   = wid >> 1;
    const int wn   = wid & 1;
    const int bt   = blockIdx.x;
    const int b    = bt >> 3;
    const int i0   = (bt & 7) << 2;
    const int co0  = blockIdx.y << 7;

    float acc[2][8][4];
#pragma unroll
    for (int mf = 0; mf < 2; mf++)
#pragma unroll
        for (int nf = 0; nf < 8; nf++)
#pragma unroll
            for (int e = 0; e < 4; e++) acc[mf][nf][e] = 0.f;

    const uint32_t a_rowoff = (uint32_t)((wm * 32 + (lane & 15)) * 144 + (lane >> 4) * 16);
    const uint32_t b_rowoff = (uint32_t)((wn * 64 + (lane & 15)) * 144 + (lane >> 4) * 16);

    conv1_issue_stage(sb, b, i0, co0, 0, 0, tid);
    cp_commit();

    int it = 0;
    for (int tap = 0; tap < 49; tap++) {
        for (int kc = 0; kc < 4; kc++, it++) {
            if (it < 195) {
                int nit = it + 1;
                conv1_issue_stage(sb + ((nit & 1) ? C1_STAGE : 0),
                                  b, i0, co0, nit >> 2, nit & 3, tid);
                cp_commit();
                cp_wait<1>();
            } else {
                cp_wait<0>();
            }
            __syncthreads();

            const uint32_t cur = sb + ((it & 1) ? C1_STAGE : 0);
#pragma unroll
            for (int ks = 0; ks < 4; ks++) {
                const uint32_t koff = (uint32_t)(ks * 32);
                uint32_t ah[2][4], am[2][4], bh[8][2], bm[8][2];
#pragma unroll
                for (int mf = 0; mf < 2; mf++) {
                    uint32_t addr = cur + a_rowoff + (uint32_t)(mf * 16 * 144) + koff;
                    ldsm4(ah[mf], addr);
                    ldsm4(am[mf], addr + C1_TILE);
                }
#pragma unroll
                for (int nf2 = 0; nf2 < 4; nf2++) {
                    uint32_t r[4];
                    uint32_t addr = cur + 2 * C1_TILE + b_rowoff + (uint32_t)(nf2 * 16 * 144) + koff;
                    ldsm4(r, addr);
                    bh[nf2 * 2][0] = r[0]; bh[nf2 * 2][1] = r[2];
                    bh[nf2 * 2 + 1][0] = r[1]; bh[nf2 * 2 + 1][1] = r[3];
                    ldsm4(r, addr + C1_TILE);
                    bm[nf2 * 2][0] = r[0]; bm[nf2 * 2][1] = r[2];
                    bm[nf2 * 2 + 1][0] = r[1]; bm[nf2 * 2 + 1][1] = r[3];
                }
#pragma unroll
                for (int mf = 0; mf < 2; mf++)
#pragma unroll
                    for (int nf = 0; nf < 8; nf++) {
                        mma_bf16(acc[mf][nf], ah[mf], bh[nf]);
                        mma_bf16(acc[mf][nf], ah[mf], bm[nf]);
                        mma_bf16(acc[mf][nf], am[mf], bh[nf]);
                    }
            }
            __syncthreads();
        }
    }

    // epilogue: +bias, split bf16 hi/mid, smem-transpose to [px][co], write g_hT
    __nv_bfloat16* hs = (__nv_bfloat16*)smem;            // [128 px][136]
    __nv_bfloat16* ms = hs + 128 * 136;
#pragma unroll
    for (int mf = 0; mf < 2; mf++) {
        int R = wm * 32 + mf * 16 + (lane >> 2);
        float bias0 = b1[co0 + R];
        float bias8 = b1[co0 + R + 8];
#pragma unroll
        for (int nf = 0; nf < 8; nf++) {
            int C = wn * 64 + nf * 8 + (lane & 3) * 2;
#pragma unroll
            for (int e = 0; e < 4; e++) {
                float v = acc[mf][nf][e] + ((e & 2) ? bias8 : bias0);
                int px = C + (e & 1);
                int co = R + ((e & 2) ? 8 : 0);
                __nv_bfloat16 hi = __float2bfloat16(v);
                hs[px * 136 + co] = hi;
                ms[px * 136 + co] = __float2bfloat16(v - __bfloat162float(hi));
            }
        }
    }
    __syncthreads();
    {
        int px = tid >> 1;
        int half = tid & 1;
        size_t dst = (((size_t)b * HWP + i0 * 32 + px) << 8) + co0 + half * 64;
        const uint4* srcH = (const uint4*)(hs + px * 136 + half * 64);
        const uint4* srcM = (const uint4*)(ms + px * 136 + half * 64);
        uint4* dH = (uint4*)(g_hThi  + dst);
        uint4* dM = (uint4*)(g_hTmid + dst);
#pragma unroll
        for (int q = 0; q < 8; q++) { dH[q] = srcH[q]; dM[q] = srcM[q]; }
    }
}

// ---------------- BN1 stats from hT (2-stage, deterministic) ----------------
__global__ void bn1_partial_kernel() {
    int p = blockIdx.x, c = threadIdx.x;
    float s = 0.f, ss = 0.f;
    size_t base = (size_t)p * 256;
    for (int j = 0; j < 256; j++) {
        size_t r = (base + j) << 8;
        float v = __bfloat162float(g_hThi[r + c]) + __bfloat162float(g_hTmid[r + c]);
        s += v; ss += v * v;
    }
    g_p1s[p * 256 + c] = s;
    g_p1ss[p * 256 + c] = ss;
}

__global__ void bn1_final_kernel(const float* __restrict__ gamma,
                                 const float* __restrict__ beta) {
    int c = blockIdx.x, t = threadIdx.x;
    __shared__ float sh[256], sh2[256];
    sh[t]  = g_p1s[t * 256 + c];
    sh2[t] = g_p1ss[t * 256 + c];
    __syncthreads();
    for (int st = 128; st > 0; st >>= 1) {
        if (t < st) { sh[t] += sh[t + st]; sh2[t] += sh2[t + st]; }
        __syncthreads();
    }
    if (t == 0) {
        float mean = sh[0] * (1.f / 65536.f);
        float var  = sh2[0] * (1.f / 65536.f) - mean * mean;
        float a = gamma[c] * rsqrtf(var + 1e-5f);
        g_a1[c] = a;
        g_d1[c] = beta[c] - mean * a;
    }
}

// ---------------- fold BN1 into conv2 weights, split bf16 ----------------
__global__ void fold2_kernel(const float* __restrict__ w2, const float* __restrict__ b2) {
    int oc = blockIdx.x;
    int c  = threadIdx.x;
    float wv = w2[oc * CIN + c];
    float wf = wv * g_a1[c];
    __nv_bfloat16 hi = __float2bfloat16(wf);
    g_w2fhi[oc * 256 + c]  = hi;
    g_w2fmid[oc * 256 + c] = __float2bfloat16(wf - __bfloat162float(hi));
    __shared__ float sh[256];
    sh[c] = wv * g_d1[c];
    __syncthreads();
    for (int st = 128; st > 0; st >>= 1) {
        if (c < st) sh[c] += sh[c + st];
        __syncthreads();
    }
    if (c == 0) g_w2beta[oc] = b2[oc] + sh[0];
}

// ---------------- shared GEMM geometry for conv2 / out (128 M x 256 N tiles) ----------------
#define T_A     18432              // 128 * 144
#define T_B     36864              // 256 * 144
#define G_STAGE (2 * T_A + 2 * T_B)  // 110592
#define G_SMEM  (2 * G_STAGE)        // 221184

// ---------------- conv2: A = w2f [oc][c], B = hT [b][px][c]; C -> g_kT [b][n][oc] ----------------
__device__ __forceinline__ void c2_issue(uint32_t base, int b, int px0, int oc0, int kc, int tid) {
    const __nv_bfloat16* Ah = g_w2fhi  + (size_t)oc0 * 256 + kc * 64;
    const __nv_bfloat16* Am = g_w2fmid + (size_t)oc0 * 256 + kc * 64;
    const __nv_bfloat16* Bh = g_hThi  + (((size_t)b * HWP + px0) << 8) + kc * 64;
    const __nv_bfloat16* Bm = g_hTmid + (((size_t)b * HWP + px0) << 8) + kc * 64;
#pragma unroll
    for (int l = 0; l < 4; l++) {
        int idx = l * 256 + tid;
        int row = idx >> 3, c16 = idx & 7;
        uint32_t off = (uint32_t)(row * 144 + c16 * 16);
        cp_async16(base + off,       Ah + row * 256 + c16 * 8, 16);
        cp_async16(base + T_A + off, Am + row * 256 + c16 * 8, 16);
    }
#pragma unroll
    for (int l = 0; l < 8; l++) {
        int idx = l * 256 + tid;
        int row = idx >> 3, c16 = idx & 7;
        uint32_t off = (uint32_t)(row * 144 + c16 * 16);
        cp_async16(base + 2 * T_A + off,       Bh + (size_t)row * 256 + c16 * 8, 16);
        cp_async16(base + 2 * T_A + T_B + off, Bm + (size_t)row * 256 + c16 * 8, 16);
    }
}

__global__ __launch_bounds__(256, 1) void conv2_mma_kernel() {
    extern __shared__ char smem[];
    const uint32_t sb = smem_u32(smem);
    const int tid = threadIdx.x, lane = tid & 31, wid = tid >> 5;
    const int wm = wid >> 1, wn = wid & 1;
    const int bx = blockIdx.x;
    const int b = bx >> 2, px0 = (bx & 3) << 8;
    const int oc0 = blockIdx.y << 7;

    float acc[2][16][4];
#pragma unroll
    for (int mf = 0; mf < 2; mf++)
#pragma unroll
        for (int nf = 0; nf < 16; nf++)
#pragma unroll
            for (int e = 0; e < 4; e++) acc[mf][nf][e] = 0.f;

    const uint32_t a_rowoff = (uint32_t)((wm * 32 + (lane & 15)) * 144 + (lane >> 4) * 16);
    const uint32_t b_rowoff = (uint32_t)((wn * 128 + (lane & 15)) * 144 + (lane >> 4) * 16);

    c2_issue(sb, b, px0, oc0, 0, tid);
    cp_commit();
    for (int it = 0; it < 4; it++) {
        if (it < 3) {
            c2_issue(sb + (uint32_t)(((it + 1) & 1) * G_STAGE), b, px0, oc0, it + 1, tid);
            cp_commit();
            cp_wait<1>();
        } else {
            cp_wait<0>();
        }
        __syncthreads();
        const uint32_t cur = sb + (uint32_t)((it & 1) * G_STAGE);
#pragma unroll
        for (int ks = 0; ks < 4; ks++) {
            const uint32_t koff = (uint32_t)(ks * 32);
            uint32_t ah[2][4], am[2][4];
#pragma unroll
            for (int mf = 0; mf < 2; mf++) {
                uint32_t addr = cur + a_rowoff + (uint32_t)(mf * 16 * 144) + koff;
                ldsm4(ah[mf], addr);
                ldsm4(am[mf], addr + T_A);
            }
#pragma unroll
            for (int h = 0; h < 2; h++) {
                uint32_t bh[8][2], bm[8][2];
#pragma unroll
                for (int j = 0; j < 4; j++) {
                    uint32_t r[4];
                    uint32_t addr = cur + 2 * T_A + b_rowoff + (uint32_t)((h * 4 + j) * 16 * 144) + koff;
                    ldsm4(r, addr);
                    bh[j * 2][0] = r[0]; bh[j * 2][1] = r[2];
                    bh[j * 2 + 1][0] = r[1]; bh[j * 2 + 1][1] = r[3];
                    ldsm4(r, addr + T_B);
                    bm[j * 2][0] = r[0]; bm[j * 2][1] = r[2];
                    bm[j * 2 + 1][0] = r[1]; bm[j * 2 + 1][1] = r[3];
                }
#pragma unroll
                for (int mf = 0; mf < 2; mf++)
#pragma unroll
                    for (int nf = 0; nf < 8; nf++) {
                        mma_bf16(acc[mf][h * 8 + nf], ah[mf], bh[nf]);
                        mma_bf16(acc[mf][h * 8 + nf], ah[mf], bm[nf]);
                        mma_bf16(acc[mf][h * 8 + nf], am[mf], bh[nf]);
                    }
            }
        }
        __syncthreads();
    }

    // epilogue: +beta2, smem transpose to [px 256][oc 128], write g_kT rows
    float* ts = (float*)smem;    // [256][132]
#pragma unroll
    for (int mf = 0; mf < 2; mf++) {
        int R = wm * 32 + mf * 16 + (lane >> 2);
        float be0 = g_w2beta[oc0 + R];
        float be8 = g_w2beta[oc0 + R + 8];
#pragma unroll
        for (int nf = 0; nf < 16; nf++) {
            int C = wn * 128 + nf * 8 + (lane & 3) * 2;
#pragma unroll
            for (int e = 0; e < 4; e++) {
                int px = C + (e & 1);
                int co = R + ((e & 2) ? 8 : 0);
                ts[px * 132 + co] = acc[mf][nf][e] + ((e & 2) ? be8 : be0);
            }
        }
    }
    __syncthreads();
    {
        int px = tid;
        const uint4* src = (const uint4*)(ts + px * 132);
        uint4* dst = (uint4*)(g_kT + (((size_t)b * HWP + px0 + px) << 10) + oc0);
#pragma unroll
        for (int q = 0; q < 32; q++) dst[q] = src[q];
    }
}

// ---------------- BN2 stats from g_kT (2-stage) ----------------
__global__ void bn2_partial_kernel() {
    int p = blockIdx.x, t = threadIdx.x;
    float s[4] = {0.f, 0.f, 0.f, 0.f}, ss[4] = {0.f, 0.f, 0.f, 0.f};
    size_t base = (size_t)p * 256;
    for (int j = 0; j < 256; j++) {
        const float* row = g_kT + ((base + j) << 10);
#pragma unroll
        for (int k = 0; k < 4; k++) {
            float v = row[t + k * 256];
            s[k] += v; ss[k] += v * v;
        }
    }
#pragma unroll
    for (int k = 0; k < 4; k++) {
        g_p2s[p * 1024 + t + k * 256]  = s[k];
        g_p2ss[p * 1024 + t + k * 256] = ss[k];
    }
}

__global__ void bn2_final_kernel(const float* __restrict__ gamma,
                                 const float* __restrict__ beta) {
    int c = blockIdx.x, t = threadIdx.x;
    __shared__ float sh[256], sh2[256];
    sh[t]  = g_p2s[t * 1024 + c];
    sh2[t] = g_p2ss[t * 1024 + c];
    __syncthreads();
    for (int st = 128; st > 0; st >>= 1) {
        if (t < st) { sh[t] += sh[t + st]; sh2[t] += sh2[t + st]; }
        __syncthreads();
    }
    if (t == 0) {
        float mean = sh[0] * (1.f / 65536.f);
        float var  = sh2[0] * (1.f / 65536.f) - mean * mean;
        float a = gamma[c] * rsqrtf(var + 1e-5f);
        g_a2[c] = a;
        g_d2[c] = beta[c] - mean * a;
    }
}

// ---------------- BN2 + softmax, row-wise on g_kT, write S^T bf16 hi/mid ----------------
__global__ void softmax_rows_kernel() {
    __shared__ float sa[LF2], sd[LF2], sred[8];
    int tid = threadIdx.x;
    for (int i = tid; i < LF2; i += 256) { sa[i] = g_a2[i]; sd[i] = g_d2[i]; }
    __syncthreads();
    size_t row0 = (size_t)blockIdx.x * 64;
    for (int j = 0; j < 64; j++) {
        size_t r = row0 + j;
        const float* src = g_kT + (r << 10);
        float e[4];
        float s = 0.f;
#pragma unroll
        for (int k = 0; k < 4; k++) {
            int oc = tid + k * 256;
            float v = src[oc] * sa[oc] + sd[oc];
            e[k] = __expf(v);
            s += e[k];
        }
#pragma unroll
        for (int o = 16; o > 0; o >>= 1) s += __shfl_xor_sync(0xffffffffu, s, o);
        if ((tid & 31) == 0) sred[tid >> 5] = s;
        __syncthreads();
        float inv = 1.f / (sred[0] + sred[1] + sred[2] + sred[3] +
                           sred[4] + sred[5] + sred[6] + sred[7]);
        __nv_bfloat16* dh = g_sThi  + (r << 10);
        __nv_bfloat16* dm = g_sTmid + (r << 10);
#pragma unroll
        for (int k = 0; k < 4; k++) {
            int oc = tid + k * 256;
            float p = e[k] * inv;
            __nv_bfloat16 hi = __float2bfloat16(p);
            dh[oc] = hi;
            dm[oc] = __float2bfloat16(p - __bfloat162float(hi));
        }
        __syncthreads();
    }
}

// ---------------- out GEMM: A = S^T [b][n][uv], B = x [b][c][uv]; C -> out[b][n][c] ----------------
__device__ __forceinline__ void out_issue(uint32_t base, int b, int n0, int kc, int tid) {
    const __nv_bfloat16* Ah = g_sThi  + (((size_t)b * HWP + n0) << 10) + kc * 64;
    const __nv_bfloat16* Am = g_sTmid + (((size_t)b * HWP + n0) << 10) + kc * 64;
    const __nv_bfloat16* Bh = g_xchi  + (((size_t)b * CIN) << 10) + kc * 64;
    const __nv_bfloat16* Bm = g_xcmid + (((size_t)b * CIN) << 10) + kc * 64;
#pragma unroll
    for (int l = 0; l < 4; l++) {
        int idx = l * 256 + tid;
        int row = idx >> 3, c16 = idx & 7;
        uint32_t off = (uint32_t)(row * 144 + c16 * 16);
        cp_async16(base + off,       Ah + ((size_t)row << 10) + c16 * 8, 16);
        cp_async16(base + T_A + off, Am + ((size_t)row << 10) + c16 * 8, 16);
    }
#pragma unroll
    for (int l = 0; l < 8; l++) {
        int idx = l * 256 + tid;
        int row = idx >> 3, c16 = idx & 7;
        uint32_t off = (uint32_t)(row * 144 + c16 * 16);
        cp_async16(base + 2 * T_A + off,       Bh + ((size_t)row << 10) + c16 * 8, 16);
        cp_async16(base + 2 * T_A + T_B + off, Bm + ((size_t)row << 10) + c16 * 8, 16);
    }
}

__global__ __launch_bounds__(256, 1) void out_mma_kernel(float* __restrict__ out) {
    extern __shared__ char smem[];
    const uint32_t sb = smem_u32(smem);
    const int tid = threadIdx.x, lane = tid & 31, wid = tid >> 5;
    const int wm = wid >> 1, wn = wid & 1;
    const int bx = blockIdx.x;
    const int b = bx >> 3, n0 = (bx & 7) << 7;

    float acc[2][16][4];
#pragma unroll
    for (int mf = 0; mf < 2; mf++)
#pragma unroll
        for (int nf = 0; nf < 16; nf++)
#pragma unroll
            for (int e = 0; e < 4; e++) acc[mf][nf][e] = 0.f;

    const uint32_t a_rowoff = (uint32_t)((wm * 32 + (lane & 15)) * 144 + (lane >> 4) * 16);
    const uint32_t b_rowoff = (uint32_t)((wn * 128 + (lane & 15)) * 144 + (lane >> 4) * 16);

    out_issue(sb, b, n0, 0, tid);
    cp_commit();
    for (int it = 0; it < 16; it++) {
        if (it < 15) {
            out_issue(sb + (uint32_t)(((it + 1) & 1) * G_STAGE), b, n0, it + 1, tid);
            cp_commit();
            cp_wait<1>();
        } else {
            cp_wait<0>();
        }
        __syncthreads();
        const uint32_t cur = sb + (uint32_t)((it & 1) * G_STAGE);
#pragma unroll
        for (int ks = 0; ks < 4; ks++) {
            const uint32_t koff = (uint32_t)(ks * 32);
            uint32_t ah[2][4], am[2][4];
#pragma unroll
            for (int mf = 0; mf < 2; mf++) {
                uint32_t addr = cur + a_rowoff + (uint32_t)(mf * 16 * 144) + koff;
                ldsm4(ah[mf], addr);
                ldsm4(am[mf], addr + T_A);
            }
#pragma unroll
            for (int h = 0; h < 2; h++) {
                uint32_t bh[8][2], bm[8][2];
#pragma unroll
                for (int j = 0; j < 4; j++) {
                    uint32_t r[4];
                    uint32_t addr = cur + 2 * T_A + b_rowoff + (uint32_t)((h * 4 + j) * 16 * 144) + koff;
                    ldsm4(r, addr);
                    bh[j * 2][0] = r[0]; bh[j * 2][1] = r[2];
                    bh[j * 2 + 1][0] = r[1]; bh[j * 2 + 1][1] = r[3];
                    ldsm4(r, addr + T_B);
                    bm[j * 2][0] = r[0]; bm[j * 2][1] = r[2];
                    bm[j * 2 + 1][0] = r[1]; bm[j * 2 + 1][1] = r[3];
                }
#pragma unroll
                for (int mf = 0; mf < 2; mf++)
#pragma unroll
                    for (int nf = 0; nf < 8; nf++) {
                        mma_bf16(acc[mf][h * 8 + nf], ah[mf], bh[nf]);
                        mma_bf16(acc[mf][h * 8 + nf], ah[mf], bm[nf]);
                        mma_bf16(acc[mf][h * 8 + nf], am[mf], bh[nf]);
                    }
            }
        }
        __syncthreads();
    }

    // epilogue: direct coalesced float2 stores to out[b][n][c]
#pragma unroll
    for (int mf = 0; mf < 2; mf++) {
        int n = n0 + wm * 32 + mf * 16 + (lane >> 2);
        float* row0 = out + ((size_t)b << 18) + (size_t)n * 256;
        float* row8 = row0 + 8 * 256;
#pragma unroll
        for (int nf = 0; nf < 16; nf++) {
            int C = wn * 128 + nf * 8 + (lane & 3) * 2;
            *(float2*)(row0 + C) = make_float2(acc[mf][nf][0], acc[mf][nf][1]);
            *(float2*)(row8 + C) = make_float2(acc[mf][nf][2], acc[mf][nf][3]);
        }
    }
}

// ---------------- launch ----------------
extern "C" void kernel_launch(void* const* d_in, const int* in_sizes, int n_in,
                              void* d_out, int out_size) {
    const float* x   = (const float*)d_in[0];
    const float* w1  = (const float*)d_in[1];
    const float* b1  = (const float*)d_in[2];
    const float* g1  = (const float*)d_in[3];
    const float* bb1 = (const float*)d_in[4];
    const float* w2  = (const float*)d_in[5];
    const float* b2  = (const float*)d_in[6];
    const float* g2  = (const float*)d_in[7];
    const float* bb2 = (const float*)d_in[8];
    float* out = (float*)d_out;

    cudaFuncSetAttribute(conv1_mma_kernel,
                         cudaFuncAttributeMaxDynamicSharedMemorySize, C1_SMEM);
    cudaFuncSetAttribute(conv2_mma_kernel,
                         cudaFuncAttributeMaxDynamicSharedMemorySize, G_SMEM);
    cudaFuncSetAttribute(out_mma_kernel,
                         cudaFuncAttributeMaxDynamicSharedMemorySize, G_SMEM);

    split_w1_kernel<<<12544, 256>>>(w1);
    split_x_kernel<<<dim3(32, 8, 64), dim3(32, 8)>>>(x);
    conv1_mma_kernel<<<dim3(512, 2), 256, C1_SMEM>>>(b1);
    bn1_partial_kernel<<<256, 256>>>();
    bn1_final_kernel<<<256, 256>>>(g1, bb1);
    fold2_kernel<<<1024, 256>>>(w2, b2);
    conv2_mma_kernel<<<dim3(256, 8), 256, G_SMEM>>>();
    bn2_partial_kernel<<<256, 256>>>();
    bn2_final_kernel<<<1024, 256>>>(g2, bb2);
    softmax_rows_kernel<<<1024, 256>>>();
    out_mma_kernel<<<512, 256, G_SMEM>>>(out);
}

// round 5
// speedup vs baseline: 2.4975x; 1.0102x over previous
#include <cuda_runtime.h>
#include <cuda_bf16.h>
#include <cstdint>
#include <cstddef>

#define BDIM 64
#define CIN  256
#define CO1  256
#define HWP  1024
#define LF2  1024

// ---------------- scratch (device globals; no allocation) ----------------
__device__ float g_kT[(size_t)BDIM * HWP * LF2];     // conv2 output, [b][n][oc] fp32 (268MB)
__device__ float g_w2beta[LF2];
__device__ float g_a1[CO1], g_d1[CO1];
__device__ float g_a2[LF2], g_d2[LF2];
__device__ float g_p1s[256 * 256],  g_p1ss[256 * 256];
__device__ float g_p2s[256 * 1024], g_p2ss[256 * 1024];
// conv1 operands
__device__ __align__(16) __nv_bfloat16 g_whi [49 * CO1 * CIN];            // [tap][co][ci]
__device__ __align__(16) __nv_bfloat16 g_wmid[49 * CO1 * CIN];
__device__ __align__(16) __nv_bfloat16 g_xhi [(size_t)BDIM * HWP * CIN];  // [b][uv][ci]
__device__ __align__(16) __nv_bfloat16 g_xmid[(size_t)BDIM * HWP * CIN];
// out-GEMM B operand: x split, original layout [b][ci][uv]
__device__ __align__(16) __nv_bfloat16 g_xchi [(size_t)BDIM * CIN * HWP];
__device__ __align__(16) __nv_bfloat16 g_xcmid[(size_t)BDIM * CIN * HWP];
// conv1 output transposed split: [b][px][c]
__device__ __align__(16) __nv_bfloat16 g_hThi [(size_t)BDIM * HWP * CIN];
__device__ __align__(16) __nv_bfloat16 g_hTmid[(size_t)BDIM * HWP * CIN];
// conv2 folded weights split: [oc][c]
__device__ __align__(16) __nv_bfloat16 g_w2fhi [LF2 * CIN];
__device__ __align__(16) __nv_bfloat16 g_w2fmid[LF2 * CIN];
// softmax output transposed split: [b][n][uv]
__device__ __align__(16) __nv_bfloat16 g_sThi [(size_t)BDIM * HWP * LF2];
__device__ __align__(16) __nv_bfloat16 g_sTmid[(size_t)BDIM * HWP * LF2];

// ---------------- family-common PTX helpers ----------------
__device__ __forceinline__ uint32_t smem_u32(const void* p) {
    uint32_t a;
    asm("{ .reg .u64 t; cvta.to.shared.u64 t, %1; cvt.u32.u64 %0, t; }" : "=r"(a) : "l"(p));
    return a;
}
__device__ __forceinline__ void cp_async16(uint32_t dst, const void* src, uint32_t srcsize) {
    asm volatile("cp.async.cg.shared.global [%0], [%1], 16, %2;"
                 :: "r"(dst), "l"(src), "r"(srcsize));
}
__device__ __forceinline__ void cp_commit() {
    asm volatile("cp.async.commit_group;");
}
template <int N> __device__ __forceinline__ void cp_wait() {
    asm volatile("cp.async.wait_group %0;" :: "n"(N));
}
__device__ __forceinline__ void ldsm4(uint32_t* r, uint32_t addr) {
    asm volatile("ldmatrix.sync.aligned.m8n8.x4.shared.b16 {%0,%1,%2,%3}, [%4];"
                 : "=r"(r[0]), "=r"(r[1]), "=r"(r[2]), "=r"(r[3]) : "r"(addr));
}
__device__ __forceinline__ void mma_bf16(float* c, const uint32_t* a, const uint32_t* b) {
    asm volatile(
        "mma.sync.aligned.m16n8k16.row.col.f32.bf16.bf16.f32 "
        "{%0,%1,%2,%3}, {%4,%5,%6,%7}, {%8,%9}, {%0,%1,%2,%3};"
        : "+f"(c[0]), "+f"(c[1]), "+f"(c[2]), "+f"(c[3])
        : "r"(a[0]), "r"(a[1]), "r"(a[2]), "r"(a[3]), "r"(b[0]), "r"(b[1]));
}

// ---------------- profiling pad (keeps conv1 at ncu's launch index 3) ----------------
__global__ void prof_pad_kernel() {}

// ---------------- prep: split w1 -> bf16 hi/mid, layout [tap][co][ci] ----------------
__global__ void split_w1_kernel(const float* __restrict__ w1) {
    int i = blockIdx.x * 256 + threadIdx.x;
    if (i >= 49 * 256 * 256) return;
    int ci = i & 255, co = (i >> 8) & 255, tap = i >> 16;
    float v = w1[(co * 256 + ci) * 49 + tap];
    __nv_bfloat16 hi = __float2bfloat16(v);
    g_whi[i]  = hi;
    g_wmid[i] = __float2bfloat16(v - __bfloat162float(hi));
}

// ---------------- prep: split x -> transposed [b][uv][ci] AND original [b][ci][uv] ----------------
__global__ void split_x_kernel(const float* __restrict__ x) {
    __shared__ float t[32][33];
    int b   = blockIdx.z;
    int uv0 = blockIdx.x << 5;
    int ci0 = blockIdx.y << 5;
    int tx = threadIdx.x, ty = threadIdx.y;   // (32, 8)
#pragma unroll
    for (int r = 0; r < 4; r++) {
        int ci = ci0 + ty + r * 8;
        float v = x[((size_t)(b * 256 + ci) << 10) + uv0 + tx];
        t[ty + r * 8][tx] = v;
        __nv_bfloat16 hi = __float2bfloat16(v);
        size_t o = ((size_t)(b * 256 + ci) << 10) + uv0 + tx;
        g_xchi[o]  = hi;
        g_xcmid[o] = __float2bfloat16(v - __bfloat162float(hi));
    }
    __syncthreads();
#pragma unroll
    for (int r = 0; r < 4; r++) {
        int uv = uv0 + ty + r * 8;
        float v = t[tx][ty + r * 8];
        __nv_bfloat16 hi = __float2bfloat16(v);
        size_t o = ((size_t)b << 18) + ((size_t)uv << 8) + ci0 + tx;
        g_xhi[o]  = hi;
        g_xmid[o] = __float2bfloat16(v - __bfloat162float(hi));
    }
}

// ---------------- conv1 via mma.sync bf16 3-product split (3-stage, 1 sync/stage) ----------------
#define C1_TILE   18432            // 128 * 144
#define C1_STAGE  (4 * C1_TILE)    // 73728
#define C1_SMEM   (3 * C1_STAGE)   // 221184

__device__ __forceinline__ void conv1_issue_stage(
    uint32_t base, int b, int i0, int co0, int tap, int kc, int tid)
{
    const int dp = (tap / 7) * 2 - 6;
    const int dq = (tap % 7) * 2 - 6;
    const __nv_bfloat16* srcAh = g_whi  + ((size_t)tap << 16) + ((size_t)co0 << 8) + (kc << 6);
    const __nv_bfloat16* srcAm = g_wmid + ((size_t)tap << 16) + ((size_t)co0 << 8) + (kc << 6);
    const __nv_bfloat16* xh = g_xhi  + ((size_t)b << 18) + (kc << 6);
    const __nv_bfloat16* xm = g_xmid + ((size_t)b << 18) + (kc << 6);
#pragma unroll
    for (int l = 0; l < 4; l++) {
        int idx = l * 256 + tid;
        int row = idx >> 3, c16 = idx & 7;
        uint32_t off = (uint32_t)(row * 144 + c16 * 16);
        cp_async16(base + off,            srcAh + row * 256 + c16 * 8, 16);
        cp_async16(base + C1_TILE + off,  srcAm + row * 256 + c16 * 8, 16);
        int u = i0 + (row >> 5) + dp;
        int v = (row & 31) + dq;
        bool in = ((unsigned)u < 32u) && ((unsigned)v < 32u);
        int pix = in ? (u * 32 + v) : 0;
        uint32_t sz = in ? 16u : 0u;
        cp_async16(base + 2 * C1_TILE + off, xh + ((size_t)pix << 8) + c16 * 8, sz);
        cp_async16(base + 3 * C1_TILE + off, xm + ((size_t)pix << 8) + c16 * 8, sz);
    }
}

__global__ __launch_bounds__(256, 1) void conv1_mma_kernel(const float* __restrict__ b1) {
    extern __shared__ char smem[];
    const uint32_t sb = smem_u32(smem);
    const int tid  = threadIdx.x;
    const int lane = tid & 31;
    const int wid  = tid >> 5;
    const int wm   = wid >> 1;
    const int wn   = wid & 1;
    const int bt   = blockIdx.x;
    const int b    = bt >> 3;
    const int i0   = (bt & 7) << 2;
    const int co0  = blockIdx.y << 7;

    float acc[2][8][4];
#pragma unroll
    for (int mf = 0; mf < 2; mf++)
#pragma unroll
        for (int nf = 0; nf < 8; nf++)
#pragma unroll
            for (int e = 0; e < 4; e++) acc[mf][nf][e] = 0.f;

    const uint32_t a_rowoff = (uint32_t)((wm * 32 + (lane & 15)) * 144 + (lane >> 4) * 16);
    const uint32_t b_rowoff = (uint32_t)((wn * 64 + (lane & 15)) * 144 + (lane >> 4) * 16);

    // prologue: fill stages 0 and 1
    conv1_issue_stage(sb,            b, i0, co0, 0, 0, tid);
    cp_commit();
    conv1_issue_stage(sb + C1_STAGE, b, i0, co0, 0, 1, tid);
    cp_commit();

    int buf = 0;       // it % 3
    int nbuf = 2;      // (it+2) % 3
    for (int it = 0; it < 196; it++) {
        // wait for stage it (issued 2 iterations earlier; <=1 newer group may stay pending)
        if (it == 195) { cp_wait<0>(); } else { cp_wait<1>(); }
        // single barrier: publishes stage it to all warps AND proves all warps are done
        // with stage it-1, whose buffer ((it+2)%3) is refilled below.
        __syncthreads();
        if (it + 2 < 196) {
            int nit = it + 2;
            conv1_issue_stage(sb + (uint32_t)nbuf * C1_STAGE,
                              b, i0, co0, nit >> 2, nit & 3, tid);
            cp_commit();
        }

        const uint32_t cur = sb + (uint32_t)buf * C1_STAGE;
#pragma unroll
        for (int ks = 0; ks < 4; ks++) {
            const uint32_t koff = (uint32_t)(ks * 32);
            uint32_t ah[2][4], am[2][4], bh[8][2], bm[8][2];
#pragma unroll
            for (int mf = 0; mf < 2; mf++) {
                uint32_t addr = cur + a_rowoff + (uint32_t)(mf * 16 * 144) + koff;
                ldsm4(ah[mf], addr);
                ldsm4(am[mf], addr + C1_TILE);
            }
#pragma unroll
            for (int nf2 = 0; nf2 < 4; nf2++) {
                uint32_t r[4];
                uint32_t addr = cur + 2 * C1_TILE + b_rowoff + (uint32_t)(nf2 * 16 * 144) + koff;
                ldsm4(r, addr);
                bh[nf2 * 2][0] = r[0]; bh[nf2 * 2][1] = r[2];
                bh[nf2 * 2 + 1][0] = r[1]; bh[nf2 * 2 + 1][1] = r[3];
                ldsm4(r, addr + C1_TILE);
                bm[nf2 * 2][0] = r[0]; bm[nf2 * 2][1] = r[2];
                bm[nf2 * 2 + 1][0] = r[1]; bm[nf2 * 2 + 1][1] = r[3];
            }
#pragma unroll
            for (int mf = 0; mf < 2; mf++)
#pragma unroll
                for (int nf = 0; nf < 8; nf++) {
                    mma_bf16(acc[mf][nf], ah[mf], bh[nf]);
                    mma_bf16(acc[mf][nf], ah[mf], bm[nf]);
                    mma_bf16(acc[mf][nf], am[mf], bh[nf]);
                }
        }
        buf  = (buf  == 2) ? 0 : buf + 1;
        nbuf = (nbuf == 2) ? 0 : nbuf + 1;
    }
    __syncthreads();   // all warps done with last stage before smem reuse in epilogue

    // epilogue: +bias, split bf16 hi/mid, smem-transpose to [px][co], write g_hT
    __nv_bfloat16* hs = (__nv_bfloat16*)smem;            // [128 px][136]
    __nv_bfloat16* ms = hs + 128 * 136;
#pragma unroll
    for (int mf = 0; mf < 2; mf++) {
        int R = wm * 32 + mf * 16 + (lane >> 2);
        float bias0 = b1[co0 + R];
        float bias8 = b1[co0 + R + 8];
#pragma unroll
        for (int nf = 0; nf < 8; nf++) {
            int C = wn * 64 + nf * 8 + (lane & 3) * 2;
#pragma unroll
            for (int e = 0; e < 4; e++) {
                float v = acc[mf][nf][e] + ((e & 2) ? bias8 : bias0);
                int px = C + (e & 1);
                int co = R + ((e & 2) ? 8 : 0);
                __nv_bfloat16 hi = __float2bfloat16(v);
                hs[px * 136 + co] = hi;
                ms[px * 136 + co] = __float2bfloat16(v - __bfloat162float(hi));
            }
        }
    }
    __syncthreads();
    {
        int px = tid >> 1;
        int half = tid & 1;
        size_t dst = (((size_t)b * HWP + i0 * 32 + px) << 8) + co0 + half * 64;
        const uint4* srcH = (const uint4*)(hs + px * 136 + half * 64);
        const uint4* srcM = (const uint4*)(ms + px * 136 + half * 64);
        uint4* dH = (uint4*)(g_hThi  + dst);
        uint4* dM = (uint4*)(g_hTmid + dst);
#pragma unroll
        for (int q = 0; q < 8; q++) { dH[q] = srcH[q]; dM[q] = srcM[q]; }
    }
}

// ---------------- BN1 stats from hT (2-stage, deterministic) ----------------
__global__ void bn1_partial_kernel() {
    int p = blockIdx.x, c = threadIdx.x;
    float s = 0.f, ss = 0.f;
    size_t base = (size_t)p * 256;
    for (int j = 0; j < 256; j++) {
        size_t r = (base + j) << 8;
        float v = __bfloat162float(g_hThi[r + c]) + __bfloat162float(g_hTmid[r + c]);
        s += v; ss += v * v;
    }
    g_p1s[p * 256 + c] = s;
    g_p1ss[p * 256 + c] = ss;
}

__global__ void bn1_final_kernel(const float* __restrict__ gamma,
                                 const float* __restrict__ beta) {
    int c = blockIdx.x, t = threadIdx.x;
    __shared__ float sh[256], sh2[256];
    sh[t]  = g_p1s[t * 256 + c];
    sh2[t] = g_p1ss[t * 256 + c];
    __syncthreads();
    for (int st = 128; st > 0; st >>= 1) {
        if (t < st) { sh[t] += sh[t + st]; sh2[t] += sh2[t + st]; }
        __syncthreads();
    }
    if (t == 0) {
        float mean = sh[0] * (1.f / 65536.f);
        float var  = sh2[0] * (1.f / 65536.f) - mean * mean;
        float a = gamma[c] * rsqrtf(var + 1e-5f);
        g_a1[c] = a;
        g_d1[c] = beta[c] - mean * a;
    }
}

// ---------------- fold BN1 into conv2 weights, split bf16 ----------------
__global__ void fold2_kernel(const float* __restrict__ w2, const float* __restrict__ b2) {
    int oc = blockIdx.x;
    int c  = threadIdx.x;
    float wv = w2[oc * CIN + c];
    float wf = wv * g_a1[c];
    __nv_bfloat16 hi = __float2bfloat16(wf);
    g_w2fhi[oc * 256 + c]  = hi;
    g_w2fmid[oc * 256 + c] = __float2bfloat16(wf - __bfloat162float(hi));
    __shared__ float sh[256];
    sh[c] = wv * g_d1[c];
    __syncthreads();
    for (int st = 128; st > 0; st >>= 1) {
        if (c < st) sh[c] += sh[c + st];
        __syncthreads();
    }
    if (c == 0) g_w2beta[oc] = b2[oc] + sh[0];
}

// ---------------- shared GEMM geometry for conv2 / out (128 M x 256 N tiles) ----------------
#define T_A     18432              // 128 * 144
#define T_B     36864              // 256 * 144
#define G_STAGE (2 * T_A + 2 * T_B)  // 110592
#define G_SMEM  (2 * G_STAGE)        // 221184

// ---------------- conv2: A = w2f [oc][c], B = hT [b][px][c]; C -> g_kT [b][n][oc] ----------------
__device__ __forceinline__ void c2_issue(uint32_t base, int b, int px0, int oc0, int kc, int tid) {
    const __nv_bfloat16* Ah = g_w2fhi  + (size_t)oc0 * 256 + kc * 64;
    const __nv_bfloat16* Am = g_w2fmid + (size_t)oc0 * 256 + kc * 64;
    const __nv_bfloat16* Bh = g_hThi  + (((size_t)b * HWP + px0) << 8) + kc * 64;
    const __nv_bfloat16* Bm = g_hTmid + (((size_t)b * HWP + px0) << 8) + kc * 64;
#pragma unroll
    for (int l = 0; l < 4; l++) {
        int idx = l * 256 + tid;
        int row = idx >> 3, c16 = idx & 7;
        uint32_t off = (uint32_t)(row * 144 + c16 * 16);
        cp_async16(base + off,       Ah + row * 256 + c16 * 8, 16);
        cp_async16(base + T_A + off, Am + row * 256 + c16 * 8, 16);
    }
#pragma unroll
    for (int l = 0; l < 8; l++) {
        int idx = l * 256 + tid;
        int row = idx >> 3, c16 = idx & 7;
        uint32_t off = (uint32_t)(row * 144 + c16 * 16);
        cp_async16(base + 2 * T_A + off,       Bh + (size_t)row * 256 + c16 * 8, 16);
        cp_async16(base + 2 * T_A + T_B + off, Bm + (size_t)row * 256 + c16 * 8, 16);
    }
}

__global__ __launch_bounds__(256, 1) void conv2_mma_kernel() {
    extern __shared__ char smem[];
    const uint32_t sb = smem_u32(smem);
    const int tid = threadIdx.x, lane = tid & 31, wid = tid >> 5;
    const int wm = wid >> 1, wn = wid & 1;
    const int bx = blockIdx.x;
    const int b = bx >> 2, px0 = (bx & 3) << 8;
    const int oc0 = blockIdx.y << 7;

    float acc[2][16][4];
#pragma unroll
    for (int mf = 0; mf < 2; mf++)
#pragma unroll
        for (int nf = 0; nf < 16; nf++)
#pragma unroll
            for (int e = 0; e < 4; e++) acc[mf][nf][e] = 0.f;

    const uint32_t a_rowoff = (uint32_t)((wm * 32 + (lane & 15)) * 144 + (lane >> 4) * 16);
    const uint32_t b_rowoff = (uint32_t)((wn * 128 + (lane & 15)) * 144 + (lane >> 4) * 16);

    c2_issue(sb, b, px0, oc0, 0, tid);
    cp_commit();
    for (int it = 0; it < 4; it++) {
        if (it < 3) {
            c2_issue(sb + (uint32_t)(((it + 1) & 1) * G_STAGE), b, px0, oc0, it + 1, tid);
            cp_commit();
            cp_wait<1>();
        } else {
            cp_wait<0>();
        }
        __syncthreads();
        const uint32_t cur = sb + (uint32_t)((it & 1) * G_STAGE);
#pragma unroll
        for (int ks = 0; ks < 4; ks++) {
            const uint32_t koff = (uint32_t)(ks * 32);
            uint32_t ah[2][4], am[2][4];
#pragma unroll
            for (int mf = 0; mf < 2; mf++) {
                uint32_t addr = cur + a_rowoff + (uint32_t)(mf * 16 * 144) + koff;
                ldsm4(ah[mf], addr);
                ldsm4(am[mf], addr + T_A);
            }
#pragma unroll
            for (int h = 0; h < 2; h++) {
                uint32_t bh[8][2], bm[8][2];
#pragma unroll
                for (int j = 0; j < 4; j++) {
                    uint32_t r[4];
                    uint32_t addr = cur + 2 * T_A + b_rowoff + (uint32_t)((h * 4 + j) * 16 * 144) + koff;
                    ldsm4(r, addr);
                    bh[j * 2][0] = r[0]; bh[j * 2][1] = r[2];
                    bh[j * 2 + 1][0] = r[1]; bh[j * 2 + 1][1] = r[3];
                    ldsm4(r, addr + T_B);
                    bm[j * 2][0] = r[0]; bm[j * 2][1] = r[2];
                    bm[j * 2 + 1][0] = r[1]; bm[j * 2 + 1][1] = r[3];
                }
#pragma unroll
                for (int mf = 0; mf < 2; mf++)
#pragma unroll
                    for (int nf = 0; nf < 8; nf++) {
                        mma_bf16(acc[mf][h * 8 + nf], ah[mf], bh[nf]);
                        mma_bf16(acc[mf][h * 8 + nf], ah[mf], bm[nf]);
                        mma_bf16(acc[mf][h * 8 + nf], am[mf], bh[nf]);
                    }
            }
        }
        __syncthreads();
    }

    // epilogue: +beta2, smem transpose to [px 256][oc 128], write g_kT rows
    float* ts = (float*)smem;    // [256][132]
#pragma unroll
    for (int mf = 0; mf < 2; mf++) {
        int R = wm * 32 + mf * 16 + (lane >> 2);
        float be0 = g_w2beta[oc0 + R];
        float be8 = g_w2beta[oc0 + R + 8];
#pragma unroll
        for (int nf = 0; nf < 16; nf++) {
            int C = wn * 128 + nf * 8 + (lane & 3) * 2;
#pragma unroll
            for (int e = 0; e < 4; e++) {
                int px = C + (e & 1);
                int co = R + ((e & 2) ? 8 : 0);
                ts[px * 132 + co] = acc[mf][nf][e] + ((e & 2) ? be8 : be0);
            }
        }
    }
    __syncthreads();
    {
        int px = tid;
        const uint4* src = (const uint4*)(ts + px * 132);
        uint4* dst = (uint4*)(g_kT + (((size_t)b * HWP + px0 + px) << 10) + oc0);
#pragma unroll
        for (int q = 0; q < 32; q++) dst[q] = src[q];
    }
}

// ---------------- BN2 stats from g_kT (2-stage) ----------------
__global__ void bn2_partial_kernel() {
    int p = blockIdx.x, t = threadIdx.x;
    float s[4] = {0.f, 0.f, 0.f, 0.f}, ss[4] = {0.f, 0.f, 0.f, 0.f};
    size_t base = (size_t)p * 256;
    for (int j = 0; j < 256; j++) {
        const float* row = g_kT + ((base + j) << 10);
#pragma unroll
        for (int k = 0; k < 4; k++) {
            float v = row[t + k * 256];
            s[k] += v; ss[k] += v * v;
        }
    }
#pragma unroll
    for (int k = 0; k < 4; k++) {
        g_p2s[p * 1024 + t + k * 256]  = s[k];
        g_p2ss[p * 1024 + t + k * 256] = ss[k];
    }
}

__global__ void bn2_final_kernel(const float* __restrict__ gamma,
                                 const float* __restrict__ beta) {
    int c = blockIdx.x, t = threadIdx.x;
    __shared__ float sh[256], sh2[256];
    sh[t]  = g_p2s[t * 1024 + c];
    sh2[t] = g_p2ss[t * 1024 + c];
    __syncthreads();
    for (int st = 128; st > 0; st >>= 1) {
        if (t < st) { sh[t] += sh[t + st]; sh2[t] += sh2[t + st]; }
        __syncthreads();
    }
    if (t == 0) {
        float mean = sh[0] * (1.f / 65536.f);
        float var  = sh2[0] * (1.f / 65536.f) - mean * mean;
        float a = gamma[c] * rsqrtf(var + 1e-5f);
        g_a2[c] = a;
        g_d2[c] = beta[c] - mean * a;
    }
}

// ---------------- BN2 + softmax, row-wise on g_kT, write S^T bf16 hi/mid ----------------
__global__ void softmax_rows_kernel() {
    __shared__ float sa[LF2], sd[LF2], sred[8];
    int tid = threadIdx.x;
    for (int i = tid; i < LF2; i += 256) { sa[i] = g_a2[i]; sd[i] = g_d2[i]; }
    __syncthreads();
    size_t row0 = (size_t)blockIdx.x * 64;
    for (int j = 0; j < 64; j++) {
        size_t r = row0 + j;
        const float* src = g_kT + (r << 10);
        float e[4];
        float s = 0.f;
#pragma unroll
        for (int k = 0; k < 4; k++) {
            int oc = tid + k * 256;
            float v = src[oc] * sa[oc] + sd[oc];
            e[k] = __expf(v);
            s += e[k];
        }
#pragma unroll
        for (int o = 16; o > 0; o >>= 1) s += __shfl_xor_sync(0xffffffffu, s, o);
        if ((tid & 31) == 0) sred[tid >> 5] = s;
        __syncthreads();
        float inv = 1.f / (sred[0] + sred[1] + sred[2] + sred[3] +
                           sred[4] + sred[5] + sred[6] + sred[7]);
        __nv_bfloat16* dh = g_sThi  + (r << 10);
        __nv_bfloat16* dm = g_sTmid + (r << 10);
#pragma unroll
        for (int k = 0; k < 4; k++) {
            int oc = tid + k * 256;
            float p = e[k] * inv;
            __nv_bfloat16 hi = __float2bfloat16(p);
            dh[oc] = hi;
            dm[oc] = __float2bfloat16(p - __bfloat162float(hi));
        }
        __syncthreads();
    }
}

// ---------------- out GEMM: A = S^T [b][n][uv], B = x [b][c][uv]; C -> out[b][n][c] ----------------
__device__ __forceinline__ void out_issue(uint32_t base, int b, int n0, int kc, int tid) {
    const __nv_bfloat16* Ah = g_sThi  + (((size_t)b * HWP + n0) << 10) + kc * 64;
    const __nv_bfloat16* Am = g_sTmid + (((size_t)b * HWP + n0) << 10) + kc * 64;
    const __nv_bfloat16* Bh = g_xchi  + (((size_t)b * CIN) << 10) + kc * 64;
    const __nv_bfloat16* Bm = g_xcmid + (((size_t)b * CIN) << 10) + kc * 64;
#pragma unroll
    for (int l = 0; l < 4; l++) {
        int idx = l * 256 + tid;
        int row = idx >> 3, c16 = idx & 7;
        uint32_t off = (uint32_t)(row * 144 + c16 * 16);
        cp_async16(base + off,       Ah + ((size_t)row << 10) + c16 * 8, 16);
        cp_async16(base + T_A + off, Am + ((size_t)row << 10) + c16 * 8, 16);
    }
#pragma unroll
    for (int l = 0; l < 8; l++) {
        int idx = l * 256 + tid;
        int row = idx >> 3, c16 = idx & 7;
        uint32_t off = (uint32_t)(row * 144 + c16 * 16);
        cp_async16(base + 2 * T_A + off,       Bh + ((size_t)row << 10) + c16 * 8, 16);
        cp_async16(base + 2 * T_A + T_B + off, Bm + ((size_t)row << 10) + c16 * 8, 16);
    }
}

__global__ __launch_bounds__(256, 1) void out_mma_kernel(float* __restrict__ out) {
    extern __shared__ char smem[];
    const uint32_t sb = smem_u32(smem);
    const int tid = threadIdx.x, lane = tid & 31, wid = tid >> 5;
    const int wm = wid >> 1, wn = wid & 1;
    const int bx = blockIdx.x;
    const int b = bx >> 3, n0 = (bx & 7) << 7;

    float acc[2][16][4];
#pragma unroll
    for (int mf = 0; mf < 2; mf++)
#pragma unroll
        for (int nf = 0; nf < 16; nf++)
#pragma unroll
            for (int e = 0; e < 4; e++) acc[mf][nf][e] = 0.f;

    const uint32_t a_rowoff = (uint32_t)((wm * 32 + (lane & 15)) * 144 + (lane >> 4) * 16);
    const uint32_t b_rowoff = (uint32_t)((wn * 128 + (lane & 15)) * 144 + (lane >> 4) * 16);

    out_issue(sb, b, n0, 0, tid);
    cp_commit();
    for (int it = 0; it < 16; it++) {
        if (it < 15) {
            out_issue(sb + (uint32_t)(((it + 1) & 1) * G_STAGE), b, n0, it + 1, tid);
            cp_commit();
            cp_wait<1>();
        } else {
            cp_wait<0>();
        }
        __syncthreads();
        const uint32_t cur = sb + (uint32_t)((it & 1) * G_STAGE);
#pragma unroll
        for (int ks = 0; ks < 4; ks++) {
            const uint32_t koff = (uint32_t)(ks * 32);
            uint32_t ah[2][4], am[2][4];
#pragma unroll
            for (int mf = 0; mf < 2; mf++) {
                uint32_t addr = cur + a_rowoff + (uint32_t)(mf * 16 * 144) + koff;
                ldsm4(ah[mf], addr);
                ldsm4(am[mf], addr + T_A);
            }
#pragma unroll
            for (int h = 0; h < 2; h++) {
                uint32_t bh[8][2], bm[8][2];
#pragma unroll
                for (int j = 0; j < 4; j++) {
                    uint32_t r[4];
                    uint32_t addr = cur + 2 * T_A + b_rowoff + (uint32_t)((h * 4 + j) * 16 * 144) + koff;
                    ldsm4(r, addr);
                    bh[j * 2][0] = r[0]; bh[j * 2][1] = r[2];
                    bh[j * 2 + 1][0] = r[1]; bh[j * 2 + 1][1] = r[3];
                    ldsm4(r, addr + T_B);
                    bm[j * 2][0] = r[0]; bm[j * 2][1] = r[2];
                    bm[j * 2 + 1][0] = r[1]; bm[j * 2 + 1][1] = r[3];
                }
#pragma unroll
                for (int mf = 0; mf < 2; mf++)
#pragma unroll
                    for (int nf = 0; nf < 8; nf++) {
                        mma_bf16(acc[mf][h * 8 + nf], ah[mf], bh[nf]);
                        mma_bf16(acc[mf][h * 8 + nf], ah[mf], bm[nf]);
                        mma_bf16(acc[mf][h * 8 + nf], am[mf], bh[nf]);
                    }
            }
        }
        __syncthreads();
    }

    // epilogue: direct coalesced float2 stores to out[b][n][c]
#pragma unroll
    for (int mf = 0; mf < 2; mf++) {
        int n = n0 + wm * 32 + mf * 16 + (lane >> 2);
        float* row0 = out + ((size_t)b << 18) + (size_t)n * 256;
        float* row8 = row0 + 8 * 256;
#pragma unroll
        for (int nf = 0; nf < 16; nf++) {
            int C = wn * 128 + nf * 8 + (lane & 3) * 2;
            *(float2*)(row0 + C) = make_float2(acc[mf][nf][0], acc[mf][nf][1]);
            *(float2*)(row8 + C) = make_float2(acc[mf][nf][2], acc[mf][nf][3]);
        }
    }
}

// ---------------- launch ----------------
extern "C" void kernel_launch(void* const* d_in, const int* in_sizes, int n_in,
                              void* d_out, int out_size) {
    const float* x   = (const float*)d_in[0];
    const float* w1  = (const float*)d_in[1];
    const float* b1  = (const float*)d_in[2];
    const float* g1  = (const float*)d_in[3];
    const float* bb1 = (const float*)d_in[4];
    const float* w2  = (const float*)d_in[5];
    const float* b2  = (const float*)d_in[6];
    const float* g2  = (const float*)d_in[7];
    const float* bb2 = (const float*)d_in[8];
    float* out = (float*)d_out;

    cudaFuncSetAttribute(conv1_mma_kernel,
                         cudaFuncAttributeMaxDynamicSharedMemorySize, C1_SMEM);
    cudaFuncSetAttribute(conv2_mma_kernel,
                         cudaFuncAttributeMaxDynamicSharedMemorySize, G_SMEM);
    cudaFuncSetAttribute(out_mma_kernel,
                         cudaFuncAttributeMaxDynamicSharedMemorySize, G_SMEM);

    split_w1_kernel<<<12544, 256>>>(w1);
    split_x_kernel<<<dim3(32, 8, 64), dim3(32, 8)>>>(x);
    prof_pad_kernel<<<1, 32>>>();                       // keeps conv1 at ncu launch idx 3
    conv1_mma_kernel<<<dim3(512, 2), 256, C1_SMEM>>>(b1);
    bn1_partial_kernel<<<256, 256>>>();
    bn1_final_kernel<<<256, 256>>>(g1, bb1);
    fold2_kernel<<<1024, 256>>>(w2, b2);
    conv2_mma_kernel<<<dim3(256, 8), 256, G_SMEM>>>();
    bn2_partial_kernel<<<256, 256>>>();
    bn2_final_kernel<<<1024, 256>>>(g2, bb2);
    softmax_rows_kernel<<<1024, 256>>>();
    out_mma_kernel<<<512, 256, G_SMEM>>>(out);
}

// round 6
// speedup vs baseline: 2.5465x; 1.0196x over previous
#include <cuda_runtime.h>
#include <cuda_bf16.h>
#include <cstdint>
#include <cstddef>

#define BDIM 64
#define CIN  256
#define CO1  256
#define HWP  1024
#define LF2  1024

// ---------------- scratch (device globals; no allocation) ----------------
__device__ float g_kT[(size_t)BDIM * HWP * LF2];     // conv2 output, [b][n][oc] fp32 (268MB)
__device__ float g_w2beta[LF2];
__device__ float g_a1[CO1], g_d1[CO1];
__device__ float g_a2[LF2], g_d2[LF2];
__device__ float g_p1s[256 * 256],  g_p1ss[256 * 256];
__device__ float g_p2s[256 * 1024], g_p2ss[256 * 1024];
// conv1 operands
__device__ __align__(16) __nv_bfloat16 g_whi [49 * CO1 * CIN];            // [tap][co][ci]
__device__ __align__(16) __nv_bfloat16 g_wmid[49 * CO1 * CIN];
__device__ __align__(16) __nv_bfloat16 g_xhi [(size_t)BDIM * HWP * CIN];  // [b][uv][ci]
__device__ __align__(16) __nv_bfloat16 g_xmid[(size_t)BDIM * HWP * CIN];
// out-GEMM B operand: x split, original layout [b][ci][uv]
__device__ __align__(16) __nv_bfloat16 g_xchi [(size_t)BDIM * CIN * HWP];
__device__ __align__(16) __nv_bfloat16 g_xcmid[(size_t)BDIM * CIN * HWP];
// conv1 output transposed split: [b][px][c]
__device__ __align__(16) __nv_bfloat16 g_hThi [(size_t)BDIM * HWP * CIN];
__device__ __align__(16) __nv_bfloat16 g_hTmid[(size_t)BDIM * HWP * CIN];
// conv2 folded weights split: [oc][c]
__device__ __align__(16) __nv_bfloat16 g_w2fhi [LF2 * CIN];
__device__ __align__(16) __nv_bfloat16 g_w2fmid[LF2 * CIN];
// softmax output transposed split: [b][n][uv]
__device__ __align__(16) __nv_bfloat16 g_sThi [(size_t)BDIM * HWP * LF2];
__device__ __align__(16) __nv_bfloat16 g_sTmid[(size_t)BDIM * HWP * LF2];

// ---------------- family-common PTX helpers ----------------
__device__ __forceinline__ uint32_t smem_u32(const void* p) {
    uint32_t a;
    asm("{ .reg .u64 t; cvta.to.shared.u64 t, %1; cvt.u32.u64 %0, t; }" : "=r"(a) : "l"(p));
    return a;
}
__device__ __forceinline__ void cp_async16(uint32_t dst, const void* src, uint32_t srcsize) {
    asm volatile("cp.async.cg.shared.global [%0], [%1], 16, %2;"
                 :: "r"(dst), "l"(src), "r"(srcsize));
}
__device__ __forceinline__ void cp_commit() {
    asm volatile("cp.async.commit_group;");
}
template <int N> __device__ __forceinline__ void cp_wait() {
    asm volatile("cp.async.wait_group %0;" :: "n"(N));
}
__device__ __forceinline__ void ldsm4(uint32_t* r, uint32_t addr) {
    asm volatile("ldmatrix.sync.aligned.m8n8.x4.shared.b16 {%0,%1,%2,%3}, [%4];"
                 : "=r"(r[0]), "=r"(r[1]), "=r"(r[2]), "=r"(r[3]) : "r"(addr));
}
__device__ __forceinline__ void mma_bf16(float* c, const uint32_t* a, const uint32_t* b) {
    asm volatile(
        "mma.sync.aligned.m16n8k16.row.col.f32.bf16.bf16.f32 "
        "{%0,%1,%2,%3}, {%4,%5,%6,%7}, {%8,%9}, {%0,%1,%2,%3};"
        : "+f"(c[0]), "+f"(c[1]), "+f"(c[2]), "+f"(c[3])
        : "r"(a[0]), "r"(a[1]), "r"(a[2]), "r"(a[3]), "r"(b[0]), "r"(b[1]));
}

// ---------------- profiling pad (keeps conv1 at ncu's launch index 3) ----------------
__global__ void prof_pad_kernel() {}

// ---------------- prep: split w1 -> bf16 hi/mid, layout [tap][co][ci] ----------------
__global__ void split_w1_kernel(const float* __restrict__ w1) {
    int i = blockIdx.x * 256 + threadIdx.x;
    if (i >= 49 * 256 * 256) return;
    int ci = i & 255, co = (i >> 8) & 255, tap = i >> 16;
    float v = w1[(co * 256 + ci) * 49 + tap];
    __nv_bfloat16 hi = __float2bfloat16(v);
    g_whi[i]  = hi;
    g_wmid[i] = __float2bfloat16(v - __bfloat162float(hi));
}

// ---------------- prep: split x -> transposed [b][uv][ci] AND original [b][ci][uv] ----------------
__global__ void split_x_kernel(const float* __restrict__ x) {
    __shared__ float t[32][33];
    int b   = blockIdx.z;
    int uv0 = blockIdx.x << 5;
    int ci0 = blockIdx.y << 5;
    int tx = threadIdx.x, ty = threadIdx.y;   // (32, 8)
#pragma unroll
    for (int r = 0; r < 4; r++) {
        int ci = ci0 + ty + r * 8;
        float v = x[((size_t)(b * 256 + ci) << 10) + uv0 + tx];
        t[ty + r * 8][tx] = v;
        __nv_bfloat16 hi = __float2bfloat16(v);
        size_t o = ((size_t)(b * 256 + ci) << 10) + uv0 + tx;
        g_xchi[o]  = hi;
        g_xcmid[o] = __float2bfloat16(v - __bfloat162float(hi));
    }
    __syncthreads();
#pragma unroll
    for (int r = 0; r < 4; r++) {
        int uv = uv0 + ty + r * 8;
        float v = t[tx][ty + r * 8];
        __nv_bfloat16 hi = __float2bfloat16(v);
        size_t o = ((size_t)b << 18) + ((size_t)uv << 8) + ci0 + tx;
        g_xhi[o]  = hi;
        g_xmid[o] = __float2bfloat16(v - __bfloat162float(hi));
    }
}

// ---------------- conv1 via mma.sync bf16 3-product split ----------------
// K=32 stages (49 taps x 8 ci-chunks = 392), 80B rows, 2 buffers = 80KB -> 2 CTAs/SM.
#define C1_ROW    80
#define C1_TILE   (128 * C1_ROW)     // 10240
#define C1_STAGE  (4 * C1_TILE)      // 40960
#define C1_SMEM   (2 * C1_STAGE)     // 81920

__device__ __forceinline__ void conv1_issue_stage(
    uint32_t base, int b, int i0, int co0, int tap, int kc, int tid)
{
    const int dp = (tap / 7) * 2 - 6;
    const int dq = (tap % 7) * 2 - 6;
    const __nv_bfloat16* srcAh = g_whi  + ((size_t)tap << 16) + ((size_t)co0 << 8) + (kc << 5);
    const __nv_bfloat16* srcAm = g_wmid + ((size_t)tap << 16) + ((size_t)co0 << 8) + (kc << 5);
    const __nv_bfloat16* xh = g_xhi  + ((size_t)b << 18) + (kc << 5);
    const __nv_bfloat16* xm = g_xmid + ((size_t)b << 18) + (kc << 5);
#pragma unroll
    for (int l = 0; l < 2; l++) {
        int idx = l * 256 + tid;            // 0..511
        int row = idx >> 2, c16 = idx & 3;  // row 0..127, 16B chunk 0..3
        uint32_t off = (uint32_t)(row * C1_ROW + c16 * 16);
        cp_async16(base + off,            srcAh + row * 256 + c16 * 8, 16);
        cp_async16(base + C1_TILE + off,  srcAm + row * 256 + c16 * 8, 16);
        int u = i0 + (row >> 5) + dp;
        int v = (row & 31) + dq;
        bool in = ((unsigned)u < 32u) && ((unsigned)v < 32u);
        int pix = in ? (u * 32 + v) : 0;
        uint32_t sz = in ? 16u : 0u;
        cp_async16(base + 2 * C1_TILE + off, xh + ((size_t)pix << 8) + c16 * 8, sz);
        cp_async16(base + 3 * C1_TILE + off, xm + ((size_t)pix << 8) + c16 * 8, sz);
    }
}

__global__ __launch_bounds__(256, 2) void conv1_mma_kernel(const float* __restrict__ b1) {
    extern __shared__ char smem[];
    const uint32_t sb = smem_u32(smem);
    const int tid  = threadIdx.x;
    const int lane = tid & 31;
    const int wid  = tid >> 5;
    const int wm   = wid >> 1;
    const int wn   = wid & 1;
    const int bt   = blockIdx.x;
    const int b    = bt >> 3;
    const int i0   = (bt & 7) << 2;
    const int co0  = blockIdx.y << 7;

    float acc[2][8][4];
#pragma unroll
    for (int mf = 0; mf < 2; mf++)
#pragma unroll
        for (int nf = 0; nf < 8; nf++)
#pragma unroll
            for (int e = 0; e < 4; e++) acc[mf][nf][e] = 0.f;

    const uint32_t a_rowoff = (uint32_t)((wm * 32 + (lane & 15)) * C1_ROW + (lane >> 4) * 16);
    const uint32_t b_rowoff = (uint32_t)((wn * 64 + (lane & 15)) * C1_ROW + (lane >> 4) * 16);

    // prologue: stage 0
    conv1_issue_stage(sb, b, i0, co0, 0, 0, tid);
    cp_commit();

    int buf = 0;
    for (int it = 0; it < 392; it++) {
        cp_wait<0>();          // stage it landed (issued prev iter / prologue)
        __syncthreads();       // publish stage it; all warps are done with stage it-1
        if (it + 1 < 392) {
            int nit = it + 1;
            conv1_issue_stage(sb + (uint32_t)(buf ^ 1) * C1_STAGE,
                              b, i0, co0, nit >> 3, nit & 7, tid);
            cp_commit();
        }

        const uint32_t cur = sb + (uint32_t)buf * C1_STAGE;
#pragma unroll
        for (int ks = 0; ks < 2; ks++) {
            const uint32_t koff = (uint32_t)(ks * 32);
            uint32_t ah[2][4], am[2][4];
#pragma unroll
            for (int mf = 0; mf < 2; mf++) {
                uint32_t addr = cur + a_rowoff + (uint32_t)(mf * 16 * C1_ROW) + koff;
                ldsm4(ah[mf], addr);
                ldsm4(am[mf], addr + C1_TILE);
            }
#pragma unroll
            for (int half = 0; half < 2; half++) {
                uint32_t bh[4][2], bm[4][2];
#pragma unroll
                for (int j = 0; j < 2; j++) {
                    int nf2 = half * 2 + j;
                    uint32_t r[4];
                    uint32_t addr = cur + 2 * C1_TILE + b_rowoff
                                  + (uint32_t)(nf2 * 16 * C1_ROW) + koff;
                    ldsm4(r, addr);
                    bh[j * 2][0] = r[0]; bh[j * 2][1] = r[2];
                    bh[j * 2 + 1][0] = r[1]; bh[j * 2 + 1][1] = r[3];
                    ldsm4(r, addr + C1_TILE);
                    bm[j * 2][0] = r[0]; bm[j * 2][1] = r[2];
                    bm[j * 2 + 1][0] = r[1]; bm[j * 2 + 1][1] = r[3];
                }
#pragma unroll
                for (int mf = 0; mf < 2; mf++)
#pragma unroll
                    for (int j = 0; j < 4; j++) {
                        mma_bf16(acc[mf][half * 4 + j], ah[mf], bh[j]);
                        mma_bf16(acc[mf][half * 4 + j], ah[mf], bm[j]);
                        mma_bf16(acc[mf][half * 4 + j], am[mf], bh[j]);
                    }
            }
        }
        buf ^= 1;
    }
    __syncthreads();   // all warps done with last stage before smem reuse in epilogue

    // epilogue: +bias, split bf16 hi/mid, smem-transpose to [px][co], write g_hT
    __nv_bfloat16* hs = (__nv_bfloat16*)smem;            // [128 px][136]
    __nv_bfloat16* ms = hs + 128 * 136;
#pragma unroll
    for (int mf = 0; mf < 2; mf++) {
        int R = wm * 32 + mf * 16 + (lane >> 2);
        float bias0 = b1[co0 + R];
        float bias8 = b1[co0 + R + 8];
#pragma unroll
        for (int nf = 0; nf < 8; nf++) {
            int C = wn * 64 + nf * 8 + (lane & 3) * 2;
#pragma unroll
            for (int e = 0; e < 4; e++) {
                float v = acc[mf][nf][e] + ((e & 2) ? bias8 : bias0);
                int px = C + (e & 1);
                int co = R + ((e & 2) ? 8 : 0);
                __nv_bfloat16 hi = __float2bfloat16(v);
                hs[px * 136 + co] = hi;
                ms[px * 136 + co] = __float2bfloat16(v - __bfloat162float(hi));
            }
        }
    }
    __syncthreads();
    {
        int px = tid >> 1;
        int half = tid & 1;
        size_t dst = (((size_t)b * HWP + i0 * 32 + px) << 8) + co0 + half * 64;
        const uint4* srcH = (const uint4*)(hs + px * 136 + half * 64);
        const uint4* srcM = (const uint4*)(ms + px * 136 + half * 64);
        uint4* dH = (uint4*)(g_hThi  + dst);
        uint4* dM = (uint4*)(g_hTmid + dst);
#pragma unroll
        for (int q = 0; q < 8; q++) { dH[q] = srcH[q]; dM[q] = srcM[q]; }
    }
}

// ---------------- BN1 stats from hT (2-stage, deterministic) ----------------
__global__ void bn1_partial_kernel() {
    int p = blockIdx.x, c = threadIdx.x;
    float s = 0.f, ss = 0.f;
    size_t base = (size_t)p * 256;
    for (int j = 0; j < 256; j++) {
        size_t r = (base + j) << 8;
        float v = __bfloat162float(g_hThi[r + c]) + __bfloat162float(g_hTmid[r + c]);
        s += v; ss += v * v;
    }
    g_p1s[p * 256 + c] = s;
    g_p1ss[p * 256 + c] = ss;
}

__global__ void bn1_final_kernel(const float* __restrict__ gamma,
                                 const float* __restrict__ beta) {
    int c = blockIdx.x, t = threadIdx.x;
    __shared__ float sh[256], sh2[256];
    sh[t]  = g_p1s[t * 256 + c];
    sh2[t] = g_p1ss[t * 256 + c];
    __syncthreads();
    for (int st = 128; st > 0; st >>= 1) {
        if (t < st) { sh[t] += sh[t + st]; sh2[t] += sh2[t + st]; }
        __syncthreads();
    }
    if (t == 0) {
        float mean = sh[0] * (1.f / 65536.f);
        float var  = sh2[0] * (1.f / 65536.f) - mean * mean;
        float a = gamma[c] * rsqrtf(var + 1e-5f);
        g_a1[c] = a;
        g_d1[c] = beta[c] - mean * a;
    }
}

// ---------------- fold BN1 into conv2 weights, split bf16 ----------------
__global__ void fold2_kernel(const float* __restrict__ w2, const float* __restrict__ b2) {
    int oc = blockIdx.x;
    int c  = threadIdx.x;
    float wv = w2[oc * CIN + c];
    float wf = wv * g_a1[c];
    __nv_bfloat16 hi = __float2bfloat16(wf);
    g_w2fhi[oc * 256 + c]  = hi;
    g_w2fmid[oc * 256 + c] = __float2bfloat16(wf - __bfloat162float(hi));
    __shared__ float sh[256];
    sh[c] = wv * g_d1[c];
    __syncthreads();
    for (int st = 128; st > 0; st >>= 1) {
        if (c < st) sh[c] += sh[c + st];
        __syncthreads();
    }
    if (c == 0) g_w2beta[oc] = b2[oc] + sh[0];
}

// ---------------- shared GEMM geometry for conv2 / out (128 M x 256 N tiles) ----------------
#define T_A     18432              // 128 * 144
#define T_B     36864              // 256 * 144
#define G_STAGE (2 * T_A + 2 * T_B)  // 110592
#define G_SMEM  (2 * G_STAGE)        // 221184

// ---------------- conv2: A = w2f [oc][c], B = hT [b][px][c]; C -> g_kT [b][n][oc] ----------------
__device__ __forceinline__ void c2_issue(uint32_t base, int b, int px0, int oc0, int kc, int tid) {
    const __nv_bfloat16* Ah = g_w2fhi  + (size_t)oc0 * 256 + kc * 64;
    const __nv_bfloat16* Am = g_w2fmid + (size_t)oc0 * 256 + kc * 64;
    const __nv_bfloat16* Bh = g_hThi  + (((size_t)b * HWP + px0) << 8) + kc * 64;
    const __nv_bfloat16* Bm = g_hTmid + (((size_t)b * HWP + px0) << 8) + kc * 64;
#pragma unroll
    for (int l = 0; l < 4; l++) {
        int idx = l * 256 + tid;
        int row = idx >> 3, c16 = idx & 7;
        uint32_t off = (uint32_t)(row * 144 + c16 * 16);
        cp_async16(base + off,       Ah + row * 256 + c16 * 8, 16);
        cp_async16(base + T_A + off, Am + row * 256 + c16 * 8, 16);
    }
#pragma unroll
    for (int l = 0; l < 8; l++) {
        int idx = l * 256 + tid;
        int row = idx >> 3, c16 = idx & 7;
        uint32_t off = (uint32_t)(row * 144 + c16 * 16);
        cp_async16(base + 2 * T_A + off,       Bh + (size_t)row * 256 + c16 * 8, 16);
        cp_async16(base + 2 * T_A + T_B + off, Bm + (size_t)row * 256 + c16 * 8, 16);
    }
}

__global__ __launch_bounds__(256, 1) void conv2_mma_kernel() {
    extern __shared__ char smem[];
    const uint32_t sb = smem_u32(smem);
    const int tid = threadIdx.x, lane = tid & 31, wid = tid >> 5;
    const int wm = wid >> 1, wn = wid & 1;
    const int bx = blockIdx.x;
    const int b = bx >> 2, px0 = (bx & 3) << 8;
    const int oc0 = blockIdx.y << 7;

    float acc[2][16][4];
#pragma unroll
    for (int mf = 0; mf < 2; mf++)
#pragma unroll
        for (int nf = 0; nf < 16; nf++)
#pragma unroll
            for (int e = 0; e < 4; e++) acc[mf][nf][e] = 0.f;

    const uint32_t a_rowoff = (uint32_t)((wm * 32 + (lane & 15)) * 144 + (lane >> 4) * 16);
    const uint32_t b_rowoff = (uint32_t)((wn * 128 + (lane & 15)) * 144 + (lane >> 4) * 16);

    c2_issue(sb, b, px0, oc0, 0, tid);
    cp_commit();
    for (int it = 0; it < 4; it++) {
        if (it < 3) {
            c2_issue(sb + (uint32_t)(((it + 1) & 1) * G_STAGE), b, px0, oc0, it + 1, tid);
            cp_commit();
            cp_wait<1>();
        } else {
            cp_wait<0>();
        }
        __syncthreads();
        const uint32_t cur = sb + (uint32_t)((it & 1) * G_STAGE);
#pragma unroll
        for (int ks = 0; ks < 4; ks++) {
            const uint32_t koff = (uint32_t)(ks * 32);
            uint32_t ah[2][4], am[2][4];
#pragma unroll
            for (int mf = 0; mf < 2; mf++) {
                uint32_t addr = cur + a_rowoff + (uint32_t)(mf * 16 * 144) + koff;
                ldsm4(ah[mf], addr);
                ldsm4(am[mf], addr + T_A);
            }
#pragma unroll
            for (int h = 0; h < 2; h++) {
                uint32_t bh[8][2], bm[8][2];
#pragma unroll
                for (int j = 0; j < 4; j++) {
                    uint32_t r[4];
                    uint32_t addr = cur + 2 * T_A + b_rowoff + (uint32_t)((h * 4 + j) * 16 * 144) + koff;
                    ldsm4(r, addr);
                    bh[j * 2][0] = r[0]; bh[j * 2][1] = r[2];
                    bh[j * 2 + 1][0] = r[1]; bh[j * 2 + 1][1] = r[3];
                    ldsm4(r, addr + T_B);
                    bm[j * 2][0] = r[0]; bm[j * 2][1] = r[2];
                    bm[j * 2 + 1][0] = r[1]; bm[j * 2 + 1][1] = r[3];
                }
#pragma unroll
                for (int mf = 0; mf < 2; mf++)
#pragma unroll
                    for (int nf = 0; nf < 8; nf++) {
                        mma_bf16(acc[mf][h * 8 + nf], ah[mf], bh[nf]);
                        mma_bf16(acc[mf][h * 8 + nf], ah[mf], bm[nf]);
                        mma_bf16(acc[mf][h * 8 + nf], am[mf], bh[nf]);
                    }
            }
        }
        __syncthreads();
    }

    // epilogue: +beta2, smem transpose to [px 256][oc 128], write g_kT rows
    float* ts = (float*)smem;    // [256][132]
#pragma unroll
    for (int mf = 0; mf < 2; mf++) {
        int R = wm * 32 + mf * 16 + (lane >> 2);
        float be0 = g_w2beta[oc0 + R];
        float be8 = g_w2beta[oc0 + R + 8];
#pragma unroll
        for (int nf = 0; nf < 16; nf++) {
            int C = wn * 128 + nf * 8 + (lane & 3) * 2;
#pragma unroll
            for (int e = 0; e < 4; e++) {
                int px = C + (e & 1);
                int co = R + ((e & 2) ? 8 : 0);
                ts[px * 132 + co] = acc[mf][nf][e] + ((e & 2) ? be8 : be0);
            }
        }
    }
    __syncthreads();
    {
        int px = tid;
        const uint4* src = (const uint4*)(ts + px * 132);
        uint4* dst = (uint4*)(g_kT + (((size_t)b * HWP + px0 + px) << 10) + oc0);
#pragma unroll
        for (int q = 0; q < 32; q++) dst[q] = src[q];
    }
}

// ---------------- BN2 stats from g_kT (2-stage) ----------------
__global__ void bn2_partial_kernel() {
    int p = blockIdx.x, t = threadIdx.x;
    float s[4] = {0.f, 0.f, 0.f, 0.f}, ss[4] = {0.f, 0.f, 0.f, 0.f};
    size_t base = (size_t)p * 256;
    for (int j = 0; j < 256; j++) {
        const float* row = g_kT + ((base + j) << 10);
#pragma unroll
        for (int k = 0; k < 4; k++) {
            float v = row[t + k * 256];
            s[k] += v; ss[k] += v * v;
        }
    }
#pragma unroll
    for (int k = 0; k < 4; k++) {
        g_p2s[p * 1024 + t + k * 256]  = s[k];
        g_p2ss[p * 1024 + t + k * 256] = ss[k];
    }
}

__global__ void bn2_final_kernel(const float* __restrict__ gamma,
                                 const float* __restrict__ beta) {
    int c = blockIdx.x, t = threadIdx.x;
    __shared__ float sh[256], sh2[256];
    sh[t]  = g_p2s[t * 1024 + c];
    sh2[t] = g_p2ss[t * 1024 + c];
    __syncthreads();
    for (int st = 128; st > 0; st >>= 1) {
        if (t < st) { sh[t] += sh[t + st]; sh2[t] += sh2[t + st]; }
        __syncthreads();
    }
    if (t == 0) {
        float mean = sh[0] * (1.f / 65536.f);
        float var  = sh2[0] * (1.f / 65536.f) - mean * mean;
        float a = gamma[c] * rsqrtf(var + 1e-5f);
        g_a2[c] = a;
        g_d2[c] = beta[c] - mean * a;
    }
}

// ---------------- BN2 + softmax, row-wise on g_kT, write S^T bf16 hi/mid ----------------
__global__ void softmax_rows_kernel() {
    __shared__ float sa[LF2], sd[LF2], sred[8];
    int tid = threadIdx.x;
    for (int i = tid; i < LF2; i += 256) { sa[i] = g_a2[i]; sd[i] = g_d2[i]; }
    __syncthreads();
    size_t row0 = (size_t)blockIdx.x * 64;
    for (int j = 0; j < 64; j++) {
        size_t r = row0 + j;
        const float* src = g_kT + (r << 10);
        float e[4];
        float s = 0.f;
#pragma unroll
        for (int k = 0; k < 4; k++) {
            int oc = tid + k * 256;
            float v = src[oc] * sa[oc] + sd[oc];
            e[k] = __expf(v);
            s += e[k];
        }
#pragma unroll
        for (int o = 16; o > 0; o >>= 1) s += __shfl_xor_sync(0xffffffffu, s, o);
        if ((tid & 31) == 0) sred[tid >> 5] = s;
        __syncthreads();
        float inv = 1.f / (sred[0] + sred[1] + sred[2] + sred[3] +
                           sred[4] + sred[5] + sred[6] + sred[7]);
        __nv_bfloat16* dh = g_sThi  + (r << 10);
        __nv_bfloat16* dm = g_sTmid + (r << 10);
#pragma unroll
        for (int k = 0; k < 4; k++) {
            int oc = tid + k * 256;
            float p = e[k] * inv;
            __nv_bfloat16 hi = __float2bfloat16(p);
            dh[oc] = hi;
            dm[oc] = __float2bfloat16(p - __bfloat162float(hi));
        }
        __syncthreads();
    }
}

// ---------------- out GEMM: A = S^T [b][n][uv], B = x [b][c][uv]; C -> out[b][n][c] ----------------
__device__ __forceinline__ void out_issue(uint32_t base, int b, int n0, int kc, int tid) {
    const __nv_bfloat16* Ah = g_sThi  + (((size_t)b * HWP + n0) << 10) + kc * 64;
    const __nv_bfloat16* Am = g_sTmid + (((size_t)b * HWP + n0) << 10) + kc * 64;
    const __nv_bfloat16* Bh = g_xchi  + (((size_t)b * CIN) << 10) + kc * 64;
    const __nv_bfloat16* Bm = g_xcmid + (((size_t)b * CIN) << 10) + kc * 64;
#pragma unroll
    for (int l = 0; l < 4; l++) {
        int idx = l * 256 + tid;
        int row = idx >> 3, c16 = idx & 7;
        uint32_t off = (uint32_t)(row * 144 + c16 * 16);
        cp_async16(base + off,       Ah + ((size_t)row << 10) + c16 * 8, 16);
        cp_async16(base + T_A + off, Am + ((size_t)row << 10) + c16 * 8, 16);
    }
#pragma unroll
    for (int l = 0; l < 8; l++) {
        int idx = l * 256 + tid;
        int row = idx >> 3, c16 = idx & 7;
        uint32_t off = (uint32_t)(row * 144 + c16 * 16);
        cp_async16(base + 2 * T_A + off,       Bh + ((size_t)row << 10) + c16 * 8, 16);
        cp_async16(base + 2 * T_A + T_B + off, Bm + ((size_t)row << 10) + c16 * 8, 16);
    }
}

__global__ __launch_bounds__(256, 1) void out_mma_kernel(float* __restrict__ out) {
    extern __shared__ char smem[];
    const uint32_t sb = smem_u32(smem);
    const int tid = threadIdx.x, lane = tid & 31, wid = tid >> 5;
    const int wm = wid >> 1, wn = wid & 1;
    const int bx = blockIdx.x;
    const int b = bx >> 3, n0 = (bx & 7) << 7;

    float acc[2][16][4];
#pragma unroll
    for (int mf = 0; mf < 2; mf++)
#pragma unroll
        for (int nf = 0; nf < 16; nf++)
#pragma unroll
            for (int e = 0; e < 4; e++) acc[mf][nf][e] = 0.f;

    const uint32_t a_rowoff = (uint32_t)((wm * 32 + (lane & 15)) * 144 + (lane >> 4) * 16);
    const uint32_t b_rowoff = (uint32_t)((wn * 128 + (lane & 15)) * 144 + (lane >> 4) * 16);

    out_issue(sb, b, n0, 0, tid);
    cp_commit();
    for (int it = 0; it < 16; it++) {
        if (it < 15) {
            out_issue(sb + (uint32_t)(((it + 1) & 1) * G_STAGE), b, n0, it + 1, tid);
            cp_commit();
            cp_wait<1>();
        } else {
            cp_wait<0>();
        }
        __syncthreads();
        const uint32_t cur = sb + (uint32_t)((it & 1) * G_STAGE);
#pragma unroll
        for (int ks = 0; ks < 4; ks++) {
            const uint32_t koff = (uint32_t)(ks * 32);
            uint32_t ah[2][4], am[2][4];
#pragma unroll
            for (int mf = 0; mf < 2; mf++) {
                uint32_t addr = cur + a_rowoff + (uint32_t)(mf * 16 * 144) + koff;
                ldsm4(ah[mf], addr);
                ldsm4(am[mf], addr + T_A);
            }
#pragma unroll
            for (int h = 0; h < 2; h++) {
                uint32_t bh[8][2], bm[8][2];
#pragma unroll
                for (int j = 0; j < 4; j++) {
                    uint32_t r[4];
                    uint32_t addr = cur + 2 * T_A + b_rowoff + (uint32_t)((h * 4 + j) * 16 * 144) + koff;
                    ldsm4(r, addr);
                    bh[j * 2][0] = r[0]; bh[j * 2][1] = r[2];
                    bh[j * 2 + 1][0] = r[1]; bh[j * 2 + 1][1] = r[3];
                    ldsm4(r, addr + T_B);
                    bm[j * 2][0] = r[0]; bm[j * 2][1] = r[2];
                    bm[j * 2 + 1][0] = r[1]; bm[j * 2 + 1][1] = r[3];
                }
#pragma unroll
                for (int mf = 0; mf < 2; mf++)
#pragma unroll
                    for (int nf = 0; nf < 8; nf++) {
                        mma_bf16(acc[mf][h * 8 + nf], ah[mf], bh[nf]);
                        mma_bf16(acc[mf][h * 8 + nf], ah[mf], bm[nf]);
                        mma_bf16(acc[mf][h * 8 + nf], am[mf], bh[nf]);
                    }
            }
        }
        __syncthreads();
    }

    // epilogue: direct coalesced float2 stores to out[b][n][c]
#pragma unroll
    for (int mf = 0; mf < 2; mf++) {
        int n = n0 + wm * 32 + mf * 16 + (lane >> 2);
        float* row0 = out + ((size_t)b << 18) + (size_t)n * 256;
        float* row8 = row0 + 8 * 256;
#pragma unroll
        for (int nf = 0; nf < 16; nf++) {
            int C = wn * 128 + nf * 8 + (lane & 3) * 2;
            *(float2*)(row0 + C) = make_float2(acc[mf][nf][0], acc[mf][nf][1]);
            *(float2*)(row8 + C) = make_float2(acc[mf][nf][2], acc[mf][nf][3]);
        }
    }
}

// ---------------- launch ----------------
extern "C" void kernel_launch(void* const* d_in, const int* in_sizes, int n_in,
                              void* d_out, int out_size) {
    const float* x   = (const float*)d_in[0];
    const float* w1  = (const float*)d_in[1];
    const float* b1  = (const float*)d_in[2];
    const float* g1  = (const float*)d_in[3];
    const float* bb1 = (const float*)d_in[4];
    const float* w2  = (const float*)d_in[5];
    const float* b2  = (const float*)d_in[6];
    const float* g2  = (const float*)d_in[7];
    const float* bb2 = (const float*)d_in[8];
    float* out = (float*)d_out;

    cudaFuncSetAttribute(conv1_mma_kernel,
                         cudaFuncAttributeMaxDynamicSharedMemorySize, C1_SMEM);
    cudaFuncSetAttribute(conv2_mma_kernel,
                         cudaFuncAttributeMaxDynamicSharedMemorySize, G_SMEM);
    cudaFuncSetAttribute(out_mma_kernel,
                         cudaFuncAttributeMaxDynamicSharedMemorySize, G_SMEM);

    split_w1_kernel<<<12544, 256>>>(w1);
    split_x_kernel<<<dim3(32, 8, 64), dim3(32, 8)>>>(x);
    prof_pad_kernel<<<1, 32>>>();                       // keeps conv1 at ncu launch idx 3
    conv1_mma_kernel<<<dim3(512, 2), 256, C1_SMEM>>>(b1);
    bn1_partial_kernel<<<256, 256>>>();
    bn1_final_kernel<<<256, 256>>>(g1, bb1);
    fold2_kernel<<<1024, 256>>>(w2, b2);
    conv2_mma_kernel<<<dim3(256, 8), 256, G_SMEM>>>();
    bn2_partial_kernel<<<256, 256>>>();
    bn2_final_kernel<<<1024, 256>>>(g2, bb2);
    softmax_rows_kernel<<<1024, 256>>>();
    out_mma_kernel<<<512, 256, G_SMEM>>>(out);
}